// round 12
// baseline (speedup 1.0000x reference)
#include <cuda_runtime.h>
#include <cuda_fp16.h>
#include <math.h>
#include <stdint.h>

#define BB 4
#define LL 1024
#define DMODEL 512
#define HH 8
#define NC 8
#define DK 64
#define LOG_AV (-4.605170185988091f)   // log(0.01)

// ---------------- scratch (device globals: no allocation allowed) ----------
__device__ __align__(256) float g_probs[2][BB][HH][LL][NC]; // 0=q,1=k
__device__ __align__(256) uint4 g_qf[BB][HH][64][8][32];
__device__ __align__(256) uint4 g_kf[BB][HH][128][4][32];
__device__ __align__(256) uint4 g_vf[BB][HH][64][8][32];
__device__ __align__(256) uint4 g_wf[4][64][32][32];
__device__ __align__(256) uint4 g_pkf[BB][HH][128][32];
__device__ __align__(256) float g_ctx[BB][LL][DMODEL];
// reduction partials (no atomics, no zeroing needed)
__device__ float g_klpart[2][BB][HH][4];
__device__ float g_Mpart[64][4][38];   // [s*32+b*8+h][chunk][36 M + dq2 + dm1]

// ---------------- helpers ---------------------------------------------------
__device__ __forceinline__ uint32_t f2tf(float x) {
    uint32_t r;
    asm("cvt.rna.tf32.f32 %0, %1;" : "=r"(r) : "f"(x));
    return r;
}
__device__ __forceinline__ void mma8(float* c, const uint32_t* a, uint32_t b0, uint32_t b1) {
    asm volatile(
        "mma.sync.aligned.m16n8k8.row.col.f32.tf32.tf32.f32 "
        "{%0,%1,%2,%3}, {%4,%5,%6,%7}, {%8,%9}, {%0,%1,%2,%3};"
        : "+f"(c[0]), "+f"(c[1]), "+f"(c[2]), "+f"(c[3])
        : "r"(a[0]), "r"(a[1]), "r"(a[2]), "r"(a[3]), "r"(b0), "r"(b1));
}
__device__ __forceinline__ void ldm4(uint32_t* r, uint32_t saddr) {
    asm volatile("ldmatrix.sync.aligned.m8n8.x4.shared.b16 {%0,%1,%2,%3}, [%4];"
        : "=r"(r[0]), "=r"(r[1]), "=r"(r[2]), "=r"(r[3]) : "r"(saddr));
}
__device__ __forceinline__ void cp16(uint32_t saddr, const void* gptr) {
    asm volatile("cp.async.cg.shared.global [%0], [%1], 16;" :: "r"(saddr), "l"(gptr));
}
__device__ __forceinline__ void cp_commit() { asm volatile("cp.async.commit_group;"); }
template<int N> __device__ __forceinline__ void cp_wait() {
    asm volatile("cp.async.wait_group %0;" :: "n"(N));
}
__device__ __forceinline__ float wred(float v) {
    v += __shfl_xor_sync(0xffffffffu, v, 16);
    v += __shfl_xor_sync(0xffffffffu, v, 8);
    v += __shfl_xor_sync(0xffffffffu, v, 4);
    v += __shfl_xor_sync(0xffffffffu, v, 2);
    v += __shfl_xor_sync(0xffffffffu, v, 1);
    return v;
}

// ---------------- weight pack (coalesced) -----------------------------------
struct PArgs { const float* W[4]; };
__global__ __launch_bounds__(256) void pack_w(PArgs pa) {
    int idx = blockIdx.x * 256 + threadIdx.x;   // 65536
    int g = idx & 7;
    int k16 = (idx >> 3) & 31;
    int n8 = (idx >> 8) & 63;
    int w = idx >> 14;
    const float* src = pa.W[w] + (size_t)(n8 * 8 + g) * 512 + k16 * 16;
    float4 v0 = *(const float4*)(src);
    float4 v1 = *(const float4*)(src + 4);
    float4 v2 = *(const float4*)(src + 8);
    float4 v3 = *(const float4*)(src + 12);
    float c0[4] = { v0.x, v0.y, v0.z, v0.w };
    float c1[4] = { v1.x, v1.y, v1.z, v1.w };
    float c2[4] = { v2.x, v2.y, v2.z, v2.w };
    float c3[4] = { v3.x, v3.y, v3.z, v3.w };
#pragma unroll
    for (int q = 0; q < 4; q++) {
        uint4 o;
        o.x = f2tf(c0[q]); o.y = f2tf(c1[q]); o.z = f2tf(c2[q]); o.w = f2tf(c3[q]);
        g_wf[w][n8][k16][g * 4 + q] = o;
    }
}

// ---------------- clustering: probs + kl partials + fused pk pack ------------
__global__ __launch_bounds__(256) void clustering_kernel(
    const float* __restrict__ qin, const float* __restrict__ kin,
    const float* __restrict__ mu, const float* __restrict__ logvar,
    const float* __restrict__ logprior)
{
    __shared__ float4 mu4[NC][16];
    __shared__ float4 iv4[NC][16];
    __shared__ float lvs_s[NC], ratio_s[NC], logp_s[NC], prior_s[NC];
    __shared__ float wsum[8];

    int bx = blockIdx.x;
    int s = bx >> 5;
    int rem = bx & 31;
    int b = rem >> 3;
    int h = rem & 7;
    int tid = threadIdx.x;
    int l = blockIdx.y * 256 + tid;

    if (tid < NC * 16) {
        int c = tid >> 4, d4 = tid & 15;
        const float* msrc = &mu[(h * NC + c) * DK + d4 * 4];
        const float* lsrc = &logvar[(h * NC + c) * DK + d4 * 4];
        float4 mv = make_float4(msrc[0], msrc[1], msrc[2], msrc[3]);
        float4 ivv = make_float4(expf(-lsrc[0]), expf(-lsrc[1]), expf(-lsrc[2]), expf(-lsrc[3]));
        mu4[c][d4] = mv;
        iv4[c][d4] = ivv;
    }
    __syncthreads();
    if (tid < NC) {
        float ls = 0.f, rs = 0.f;
        const float avar = expf(LOG_AV);
        for (int d4 = 0; d4 < 16; d4++) {
            float4 ivv = iv4[tid][d4];
            rs += ivv.x + ivv.y + ivv.z + ivv.w;
        }
        for (int d = 0; d < DK; d++)
            ls += logvar[(h * NC + tid) * DK + d];
        lvs_s[tid] = ls;
        ratio_s[tid] = avar * rs;
    }
    if (tid == 0) {
        float mx = -1e30f;
        for (int c = 0; c < NC; c++) mx = fmaxf(mx, logprior[h * NC + c]);
        float ss = 0.f;
        for (int c = 0; c < NC; c++) ss += expf(logprior[h * NC + c] - mx);
        float lse = mx + logf(ss);
        for (int c = 0; c < NC; c++) {
            logp_s[c] = logprior[h * NC + c] - lse;
            prior_s[c] = expf(logp_s[c]);
        }
    }
    __syncthreads();

    const float* src = (s == 0) ? qin : kin;
    const float4* xr4 = (const float4*)(src + ((size_t)b * LL + l) * DMODEL + h * DK);

    float4 x4[16];
#pragma unroll
    for (int dd = 0; dd < 16; dd++) x4[dd] = xr4[dd];

    float mse[NC], logit[NC];
#pragma unroll
    for (int c = 0; c < NC; c++) {
        float a = 0.f;
#pragma unroll
        for (int d4 = 0; d4 < 16; d4++) {
            float4 mv = mu4[c][d4];
            float4 ivv = iv4[c][d4];
            float t0 = x4[d4].x - mv.x; a = fmaf(t0 * t0, ivv.x, a);
            float t1 = x4[d4].y - mv.y; a = fmaf(t1 * t1, ivv.y, a);
            float t2 = x4[d4].z - mv.z; a = fmaf(t2 * t2, ivv.z, a);
            float t3 = x4[d4].w - mv.w; a = fmaf(t3 * t3, ivv.w, a);
        }
        mse[c] = a;
        logit[c] = -0.5f * a - 0.5f * lvs_s[c] + logp_s[c];
    }
    float m = logit[0];
#pragma unroll
    for (int c = 1; c < NC; c++) m = fmaxf(m, logit[c]);
    float p[NC];
    float Zl = 0.f;
#pragma unroll
    for (int c = 0; c < NC; c++) { p[c] = expf(logit[c] - m); Zl += p[c]; }
    float lz = logf(Zl);
    float inv = 1.f / Zl;

    float t1 = 0.f;
#pragma unroll
    for (int c = 0; c < NC; c++)
        t1 += prior_s[c] * (logp_s[c] - (logit[c] - m - lz));
#pragma unroll
    for (int c = 0; c < NC; c++) p[c] *= inv;
    float t2 = 0.f;
#pragma unroll
    for (int c = 0; c < NC; c++)
        t2 += p[c] * (mse[c] + ratio_s[c] + lvs_s[c]);
    float klloc = t1 + 0.5f * t2;

#pragma unroll
    for (int c = 0; c < NC; c++) g_probs[s][b][h][l][c] = p[c];

    // fused Pk fragment pack (k-side only), hi/lo tf32 split
    if (s == 1) {
        int n8 = l >> 3;
        int lanebase = (l & 7) * 4;
#pragma unroll
        for (int qq = 0; qq < 4; qq++) {
            uint32_t h0 = f2tf(p[qq]), h1 = f2tf(p[qq + 4]);
            uint32_t l0 = f2tf(p[qq] - __uint_as_float(h0));
            uint32_t l1 = f2tf(p[qq + 4] - __uint_as_float(h1));
            g_pkf[b][h][n8][lanebase + qq] = make_uint4(h0, h1, l0, l1);
        }
    }

    // block-reduce kl -> partials (no atomics)
    float v = wred(klloc);
    if ((tid & 31) == 0) wsum[tid >> 5] = v;
    __syncthreads();
    if (tid == 0) {
        float acc = 0.f;
        for (int i = 0; i < 8; i++) acc += wsum[i];
        g_klpart[s][b][h][blockIdx.y] = acc;
    }
}

// ---------------- stats: per-block partials (no atomics) --------------------
__global__ __launch_bounds__(256) void stats_kernel()
{
    __shared__ float ws[8][38];
    int sbh = blockIdx.x >> 2;
    int chunk = blockIdx.x & 3;
    int s = sbh >> 5, b = (sbh >> 3) & 3, h = sbh & 7;
    int tid = threadIdx.x, wid = tid >> 5;
    int l = chunk * 256 + tid;

    float4 pA = *(const float4*)&g_probs[s][b][h][l][0];
    float4 pB = *(const float4*)&g_probs[s][b][h][l][4];
    float p[8] = { pA.x, pA.y, pA.z, pA.w, pB.x, pB.y, pB.z, pB.w };
    float dq = 0.f;
#pragma unroll
    for (int c = 0; c < 8; c++) dq = fmaf(p[c], p[c], dq);
    float M[36];
    {
        int e = 0;
#pragma unroll
        for (int c = 0; c < 8; c++)
#pragma unroll
            for (int c2 = c; c2 < 8; c2++) M[e++] = p[c] * p[c2];
    }

#pragma unroll
    for (int e = 0; e < 36; e++) {
        float v = wred(M[e]);
        if ((tid & 31) == 0) ws[wid][e] = v;
    }
    {
        float v = wred(dq * dq);
        if ((tid & 31) == 0) ws[wid][36] = v;
        v = wred((dq - 1.f) * (dq - 1.f));
        if ((tid & 31) == 0) ws[wid][37] = v;
    }
    __syncthreads();
    if (tid < 38) {
        float acc = 0.f;
        for (int w = 0; w < 8; w++) acc += ws[w][tid];
        g_Mpart[sbh][chunk][tid] = acc;
    }
}

// ---------------- cp.async 6-stage tf32 GEMM, ldmatrix A-feed ----------------
#define GSTR 20
#define GSTAGE 18432
#define GNST 6
struct GArgs {
    const float* A[3];
    const float* Bi[3];
    float sc[3];
    int md[3];
    int ws[3];
    float* outp;
};

__global__ __launch_bounds__(256, 2) void gemm_tf32(GArgs ga)
{
    extern __shared__ uint8_t sm[];
    int z = blockIdx.z;
    const float* Ap = ga.A[z];
    if (!Ap) Ap = &g_ctx[0][0][0];
    const float* bias = ga.Bi[z];
    float scale = ga.sc[z];
    int out_mode = ga.md[z];
    int wsel = ga.ws[z];

    int tid = threadIdx.x;
    int lane = tid & 31, wid = tid >> 5;
    int g = lane >> 2, q = lane & 3;
    int wm = wid & 3, wn = wid >> 2;
    int m0 = blockIdx.y * 128, n0 = blockIdx.x * 128;
    int n8base = n0 >> 3;

    int lt = lane >> 3, lr = lane & 7;
    int ldrow = ((lt & 1) << 3) + lr;
    int ldcol = (lt & 2) << 1;

    auto issue = [&](int kc) {
        int stg = kc % GNST;
        uint32_t base = (uint32_t)__cvta_generic_to_shared(sm + stg * GSTAGE);
#pragma unroll
        for (int i = 0; i < 2; i++) {
            int cid = tid + 256 * i;
            int row = cid >> 2, c = cid & 3;
            cp16(base + (row * GSTR + c * 4) * 4,
                 Ap + (size_t)(m0 + row) * 512 + kc * 16 + c * 4);
            int n8b = cid >> 5, ln = cid & 31;
            cp16(base + 10240 + cid * 16, &g_wf[wsel][n8base + n8b][kc][ln]);
        }
        cp_commit();
    };

    float acc[2][8][4];
#pragma unroll
    for (int mt = 0; mt < 2; mt++)
#pragma unroll
        for (int nt = 0; nt < 8; nt++)
#pragma unroll
            for (int s = 0; s < 4; s++) acc[mt][nt][s] = 0.f;

    issue(0); issue(1); issue(2);

    for (int it = 0; it < 16; it++) {
        if (it == 15) cp_wait<0>(); else cp_wait<1>();
        __syncthreads();
        int c3 = 2 * it + 3, c4 = 2 * it + 4;
        if (c3 < 32) issue(c3);
        if (c4 < 32) issue(c4);

        for (int half = 0; half < 2; half++) {
            int kc = 2 * it + half;
            uint32_t As_s = (uint32_t)__cvta_generic_to_shared(sm + (kc % GNST) * GSTAGE);
            const uint4* Bsm = (const uint4*)(sm + (kc % GNST) * GSTAGE + 10240);

            uint4 bfr[8];
#pragma unroll
            for (int nt = 0; nt < 8; nt++)
                bfr[nt] = Bsm[(wn * 8 + nt) * 32 + lane];

#pragma unroll
            for (int ks = 0; ks < 2; ks++) {
                uint32_t a[2][4];
#pragma unroll
                for (int mt = 0; mt < 2; mt++) {
                    int mr = wm * 32 + mt * 16;
                    uint32_t raw[4];
                    ldm4(raw, As_s + ((mr + ldrow) * GSTR + ks * 8 + ldcol) * 4);
                    a[mt][0] = f2tf(__uint_as_float(raw[0]));
                    a[mt][1] = f2tf(__uint_as_float(raw[1]));
                    a[mt][2] = f2tf(__uint_as_float(raw[2]));
                    a[mt][3] = f2tf(__uint_as_float(raw[3]));
                }
#pragma unroll
                for (int nt = 0; nt < 8; nt++) {
                    uint32_t b0 = ks ? bfr[nt].z : bfr[nt].x;
                    uint32_t b1 = ks ? bfr[nt].w : bfr[nt].y;
                    mma8(acc[0][nt], a[0], b0, b1);
                    mma8(acc[1][nt], a[1], b0, b1);
                }
            }
        }
    }

    // ---------- staged epilogue ---------------------------------------------
    __syncthreads();
    float* S = (float*)sm + wid * 1088;
    int C0 = n0 + wn * 64;
    int hh = C0 >> 6;

#pragma unroll
    for (int mt = 0; mt < 2; mt++) {
        if (mt) __syncwarp();
#pragma unroll
        for (int nt = 0; nt < 8; nt++)
#pragma unroll
            for (int s = 0; s < 4; s++) {
                int r = g + ((s >= 2) ? 8 : 0);
                int ct = nt * 8 + 2 * q + (s & 1);
                S[r * 68 + ct] = (acc[mt][nt][s] + bias[C0 + ct]) * scale;
            }
        __syncwarp();

        int R0 = m0 + wm * 32 + mt * 16;
        if (out_mode == 3) {
#pragma unroll
            for (int it = 0; it < 8; it++) {
                int linear = it * 32 + lane;
                int row = linear >> 4, f4 = linear & 15;
                float4 v = *(const float4*)&S[row * 68 + f4 * 4];
                *(float4*)&ga.outp[(size_t)(R0 + row) * 512 + C0 + f4 * 4] = v;
            }
        } else {
            int bb = R0 >> 10;
            int l0 = R0 & 1023;
            if (out_mode == 0) {
                int l16 = l0 >> 4;
#pragma unroll
                for (int ks = 0; ks < 8; ks++) {
                    uint4 v;
                    v.x = f2tf(S[g * 68 + ks * 8 + q]);
                    v.y = f2tf(S[(g + 8) * 68 + ks * 8 + q]);
                    v.z = f2tf(S[g * 68 + ks * 8 + q + 4]);
                    v.w = f2tf(S[(g + 8) * 68 + ks * 8 + q + 4]);
                    g_qf[bb][hh][l16][ks][lane] = v;
                }
            } else if (out_mode == 1) {
#pragma unroll
                for (int j = 0; j < 2; j++)
#pragma unroll
                    for (int k16 = 0; k16 < 4; k16++) {
                        int rr = j * 8 + g;
                        uint4 v;
                        v.x = f2tf(S[rr * 68 + k16 * 16 + q]);
                        v.y = f2tf(S[rr * 68 + k16 * 16 + q + 4]);
                        v.z = f2tf(S[rr * 68 + k16 * 16 + q + 8]);
                        v.w = f2tf(S[rr * 68 + k16 * 16 + q + 12]);
                        g_kf[bb][hh][(l0 >> 3) + j][k16][lane] = v;
                    }
            } else {
                int k16v = l0 >> 4;
#pragma unroll
                for (int d8 = 0; d8 < 8; d8++) {
                    uint4 v;
                    v.x = f2tf(S[q * 68 + d8 * 8 + g]);
                    v.y = f2tf(S[(q + 4) * 68 + d8 * 8 + g]);
                    v.z = f2tf(S[(q + 8) * 68 + d8 * 8 + g]);
                    v.w = f2tf(S[(q + 12) * 68 + d8 * 8 + g]);
                    g_vf[bb][hh][k16v][d8][lane] = v;
                }
            }
        }
    }
}

// ---------------- fused flash attention: double-width stages -----------------
#define ASTG 37120

__global__ __launch_bounds__(256) void attn_tf32(const float* __restrict__ pm)
{
    extern __shared__ uint8_t sm[];

    int bh = blockIdx.x;
    int b = bh >> 3, h = bh & 7;
    int tid = threadIdx.x;
    int lane = tid & 31, w = tid >> 5;
    int g = lane >> 2, q = lane & 3;
    int q0 = blockIdx.y * 128;
    int r0 = q0 + w * 16 + g;
    int r1 = r0 + 8;

    // issue one double-tile (128 keys = subtiles 2*tt, 2*tt+1) into stage stg
    auto issue = [&](int tt, int stg) {
#pragma unroll
        for (int sub = 0; sub < 2; sub++) {
            int t = tt * 2 + sub;
            uint32_t base = (uint32_t)__cvta_generic_to_shared(sm + (stg * 2 + sub) * ASTG);
            const uint4* kg_ = &g_kf[b][h][t * 8][0][0];
            const uint4* vg_ = &g_vf[b][h][t * 4][0][0];
#pragma unroll
            for (int i = 0; i < 4; i++) {
                int cid = tid + 256 * i;
                cp16(base + cid * 16, kg_ + cid);
                cp16(base + 16384 + cid * 16, vg_ + cid);
            }
            cp16(base + 32768 + tid * 16, &g_pkf[b][h][t * 8][0] + tid);
            if (tid < 16)
                cp16(base + 36864 + tid * 16, pm + (size_t)b * LL + t * 64 + tid * 4);
        }
        cp_commit();
    };

    uint32_t qa[8][4];
    {
        int l16 = blockIdx.y * 8 + w;
#pragma unroll
        for (int ks = 0; ks < 8; ks++) {
            uint4 t0 = g_qf[b][h][l16][ks][lane];
            qa[ks][0] = t0.x; qa[ks][1] = t0.y; qa[ks][2] = t0.z; qa[ks][3] = t0.w;
        }
    }
    uint32_t ahi[4], alo[4];
    {
        float p00 = g_probs[0][b][h][r0][q];
        float p10 = g_probs[0][b][h][r1][q];
        float p04 = g_probs[0][b][h][r0][q + 4];
        float p14 = g_probs[0][b][h][r1][q + 4];
        ahi[0] = f2tf(p00); alo[0] = f2tf(p00 - __uint_as_float(ahi[0]));
        ahi[1] = f2tf(p10); alo[1] = f2tf(p10 - __uint_as_float(ahi[1]));
        ahi[2] = f2tf(p04); alo[2] = f2tf(p04 - __uint_as_float(ahi[2]));
        ahi[3] = f2tf(p14); alo[3] = f2tf(p14 - __uint_as_float(ahi[3]));
    }

    float accO[8][4];
#pragma unroll
    for (int nt = 0; nt < 8; nt++)
#pragma unroll
        for (int s = 0; s < 4; s++) accO[nt][s] = 0.f;
    float mrow0 = -1e30f, mrow1 = -1e30f, Z0 = 0.f, Z1 = 0.f;

    issue(0, 0);

    for (int tt = 0; tt < 8; tt++) {
        cp_wait<0>();
        __syncthreads();
        if (tt < 7) issue(tt + 1, (tt + 1) & 1);

        uint8_t* stbase = sm + (tt & 1) * (2 * ASTG);
        for (int sub = 0; sub < 2; sub++) {
            const uint4* Ksm = (const uint4*)(stbase + sub * ASTG);
            const uint4* Vsm = (const uint4*)(stbase + sub * ASTG + 16384);
            const uint4* Pkf = (const uint4*)(stbase + sub * ASTG + 32768);
            const float* padk = (const float*)(stbase + sub * ASTG + 36864);

            // sim = Pq·Pk^T on the tensor pipe, exact 4-term hi/lo split
            float accS[8][4];
#pragma unroll
            for (int nt = 0; nt < 8; nt++)
#pragma unroll
                for (int s = 0; s < 4; s++) accS[nt][s] = 0.f;
#pragma unroll
            for (int nt = 0; nt < 8; nt++) {
                uint4 pk = Pkf[nt * 32 + lane];
                mma8(accS[nt], ahi, pk.x, pk.y);
                mma8(accS[nt], alo, pk.x, pk.y);
                mma8(accS[nt], ahi, pk.z, pk.w);
                mma8(accS[nt], alo, pk.z, pk.w);
            }

            // sim -> bias = -10000*cmask ; u = 1-cm packed to half2
            __half2 uh0[8], uh1[8];
#pragma unroll
            for (int nt = 0; nt < 8; nt++) {
                float2 pd = *(const float2*)&padk[nt * 8 + 2 * q];
                float cm0 = fminf(fmaxf(1.f - accS[nt][0] + pd.x, 0.f), 1.f);
                float cm1 = fminf(fmaxf(1.f - accS[nt][1] + pd.y, 0.f), 1.f);
                float cm2 = fminf(fmaxf(1.f - accS[nt][2] + pd.x, 0.f), 1.f);
                float cm3 = fminf(fmaxf(1.f - accS[nt][3] + pd.y, 0.f), 1.f);
                accS[nt][0] = -10000.f * cm0;
                accS[nt][1] = -10000.f * cm1;
                accS[nt][2] = -10000.f * cm2;
                accS[nt][3] = -10000.f * cm3;
                uh0[nt] = __floats2half2_rn(1.f - cm0, 1.f - cm1);
                uh1[nt] = __floats2half2_rn(1.f - cm2, 1.f - cm3);
            }

            // S += Q * K^T
#pragma unroll
            for (int ks2 = 0; ks2 < 4; ks2++) {
#pragma unroll
                for (int nt = 0; nt < 8; nt++) {
                    uint4 kb = Ksm[(nt * 4 + ks2) * 32 + lane];
                    mma8(accS[nt], qa[2 * ks2], kb.x, kb.y);
                    mma8(accS[nt], qa[2 * ks2 + 1], kb.z, kb.w);
                }
            }

            // online softmax
            float t0 = accS[0][0], t1v = accS[0][2];
#pragma unroll
            for (int nt = 0; nt < 8; nt++) {
                t0 = fmaxf(t0, fmaxf(accS[nt][0], accS[nt][1]));
                t1v = fmaxf(t1v, fmaxf(accS[nt][2], accS[nt][3]));
            }
            t0 = fmaxf(t0, __shfl_xor_sync(0xffffffffu, t0, 1));
            t0 = fmaxf(t0, __shfl_xor_sync(0xffffffffu, t0, 2));
            t1v = fmaxf(t1v, __shfl_xor_sync(0xffffffffu, t1v, 1));
            t1v = fmaxf(t1v, __shfl_xor_sync(0xffffffffu, t1v, 2));
            float mn0 = fmaxf(mrow0, t0), mn1 = fmaxf(mrow1, t1v);
            float corr0 = __expf(mrow0 - mn0), corr1 = __expf(mrow1 - mn1);
            mrow0 = mn0; mrow1 = mn1;
            Z0 *= corr0; Z1 *= corr1;
#pragma unroll
            for (int nt = 0; nt < 8; nt++) {
                accO[nt][0] *= corr0; accO[nt][1] *= corr0;
                accO[nt][2] *= corr1; accO[nt][3] *= corr1;
            }
            float z0 = 0.f, z1 = 0.f;
#pragma unroll
            for (int nt = 0; nt < 8; nt++) {
                float e0 = __expf(accS[nt][0] - mn0);
                float e1 = __expf(accS[nt][1] - mn0);
                float e2 = __expf(accS[nt][2] - mn1);
                float e3 = __expf(accS[nt][3] - mn1);
                z0 += e0 + e1; z1 += e2 + e3;
                float2 u0 = __half22float2(uh0[nt]);
                float2 u1 = __half22float2(uh1[nt]);
                accS[nt][0] = e0 * u0.x;
                accS[nt][1] = e1 * u0.y;
                accS[nt][2] = e2 * u1.x;
                accS[nt][3] = e3 * u1.y;
            }
            Z0 += z0; Z1 += z1;

            // O += P * V : permute C-frag -> A-frag via quad shuffles
            int srcA = (lane & ~3) | (q >> 1);
            int srcB = srcA + 2;
            bool odd = (q & 1);
#pragma unroll
            for (int kg2 = 0; kg2 < 4; kg2++) {
                uint32_t aP[2][4];
#pragma unroll
                for (int half = 0; half < 2; half++) {
                    int kg = 2 * kg2 + half;
                    float x0 = __shfl_sync(0xffffffffu, accS[kg][0], srcA);
                    float x1 = __shfl_sync(0xffffffffu, accS[kg][1], srcA);
                    float x4 = __shfl_sync(0xffffffffu, accS[kg][0], srcB);
                    float x5 = __shfl_sync(0xffffffffu, accS[kg][1], srcB);
                    float y0 = __shfl_sync(0xffffffffu, accS[kg][2], srcA);
                    float y1 = __shfl_sync(0xffffffffu, accS[kg][3], srcA);
                    float y4 = __shfl_sync(0xffffffffu, accS[kg][2], srcB);
                    float y5 = __shfl_sync(0xffffffffu, accS[kg][3], srcB);
                    aP[half][0] = f2tf(odd ? x1 : x0);
                    aP[half][1] = f2tf(odd ? y1 : y0);
                    aP[half][2] = f2tf(odd ? x5 : x4);
                    aP[half][3] = f2tf(odd ? y5 : y4);
                }
#pragma unroll
                for (int nt = 0; nt < 8; nt++) {
                    uint4 vb = Vsm[(kg2 * 8 + nt) * 32 + lane];
                    mma8(accO[nt], aP[0], vb.x, vb.y);
                    mma8(accO[nt], aP[1], vb.z, vb.w);
                }
            }
        }
    }

    Z0 += __shfl_xor_sync(0xffffffffu, Z0, 1);
    Z0 += __shfl_xor_sync(0xffffffffu, Z0, 2);
    Z1 += __shfl_xor_sync(0xffffffffu, Z1, 1);
    Z1 += __shfl_xor_sync(0xffffffffu, Z1, 2);
    float iz0 = 1.f / Z0, iz1 = 1.f / Z1;
#pragma unroll
    for (int nt = 0; nt < 8; nt++) {
        float2 o0 = make_float2(accO[nt][0] * iz0, accO[nt][1] * iz0);
        float2 o1 = make_float2(accO[nt][2] * iz1, accO[nt][3] * iz1);
        *(float2*)&g_ctx[b][r0][h * DK + nt * 8 + 2 * q] = o0;
        *(float2*)&g_ctx[b][r1][h * DK + nt * 8 + 2 * q] = o1;
    }
}

// ---------------- finalize ---------------------------------------------------
__global__ void finalize_kernel(float* __restrict__ out, int out_size)
{
    int b = threadIdx.x;
    if (b >= BB) return;
    float kl = 0.f;
    for (int s = 0; s < 2; s++)
        for (int h = 0; h < HH; h++)
            for (int c = 0; c < 4; c++) kl += g_klpart[s][b][h][c];
    const float c3 = -0.5f * (1.0f + LOG_AV) * (float)DK;
    float kl_total = kl / (float)(HH * LL) + 2.f * c3;

    float dv = 0.f;
    for (int s = 0; s < 2; s++)
        for (int h = 0; h < HH; h++) {
            int sbh = s * 32 + b * 8 + h;
            float frob = 0.f;
            int e = 0;
            for (int c = 0; c < NC; c++)
                for (int c2 = c; c2 < NC; c2++) {
                    float mv = 0.f;
                    for (int ch = 0; ch < 4; ch++) mv += g_Mpart[sbh][ch][e];
                    e++;
                    frob += (c2 == c) ? mv * mv : 2.f * mv * mv;
                }
            float dq2 = 0.f, dm1 = 0.f;
            for (int ch = 0; ch < 4; ch++) {
                dq2 += g_Mpart[sbh][ch][36];
                dm1 += g_Mpart[sbh][ch][37];
            }
            dv += 0.75f * (frob - dq2) + 1.25f * dm1;
        }
    dv /= (float)HH * (float)LL * (float)LL;

    long base = (long)BB * LL * DMODEL;
    if (out_size >= base + 2 * BB) {
        out[base + b] = kl_total;
        out[base + BB + b] = dv;
    }
}

// ---------------- launch -----------------------------------------------------
extern "C" void kernel_launch(void* const* d_in, const int* in_sizes, int n_in,
                              void* d_out, int out_size)
{
    const float* query  = (const float*)d_in[0];
    const float* key    = (const float*)d_in[1];
    const float* value  = (const float*)d_in[2];
    const float* pmask  = (const float*)d_in[3];
    const float* Wq = (const float*)d_in[4];
    const float* bq = (const float*)d_in[5];
    const float* Wk = (const float*)d_in[6];
    const float* bk = (const float*)d_in[7];
    const float* Wv = (const float*)d_in[8];
    const float* bv = (const float*)d_in[9];
    const float* Wo = (const float*)d_in[10];
    const float* bo = (const float*)d_in[11];
    const float* tok_mu = (const float*)d_in[12];
    const float* tok_lv = (const float*)d_in[13];
    const float* tok_lp = (const float*)d_in[14];
    float* outp = (float*)d_out;

    cudaFuncSetAttribute(gemm_tf32, cudaFuncAttributeMaxDynamicSharedMemorySize, GNST * GSTAGE);
    cudaFuncSetAttribute(attn_tf32, cudaFuncAttributeMaxDynamicSharedMemorySize, 4 * ASTG);

    cudaStream_t sB;
    cudaStreamCreateWithFlags(&sB, cudaStreamNonBlocking);
    cudaEvent_t evFork, evProbs, evStats;
    cudaEventCreateWithFlags(&evFork, cudaEventDisableTiming);
    cudaEventCreateWithFlags(&evProbs, cudaEventDisableTiming);
    cudaEventCreateWithFlags(&evStats, cudaEventDisableTiming);

    cudaEventRecord(evFork, 0);
    cudaStreamWaitEvent(sB, evFork, 0);

    // branch B: clustering (writes probs + pkf + kl partials) -> stats
    clustering_kernel<<<dim3(2 * BB * HH, 4), 256, 0, sB>>>(query, key, tok_mu, tok_lv, tok_lp);
    cudaEventRecord(evProbs, sB);
    stats_kernel<<<256, 256, 0, sB>>>();
    cudaEventRecord(evStats, sB);

    // branch A: pack_w -> QKV gemm
    PArgs pw;
    pw.W[0] = Wq; pw.W[1] = Wk; pw.W[2] = Wv; pw.W[3] = Wo;
    pack_w<<<256, 256>>>(pw);

    GArgs qkv;
    qkv.A[0] = query; qkv.A[1] = key; qkv.A[2] = value;
    qkv.Bi[0] = bq;   qkv.Bi[1] = bk; qkv.Bi[2] = bv;
    qkv.sc[0] = 0.125f; qkv.sc[1] = 1.f; qkv.sc[2] = 1.f;
    qkv.md[0] = 0; qkv.md[1] = 1; qkv.md[2] = 2;
    qkv.ws[0] = 0; qkv.ws[1] = 1; qkv.ws[2] = 2;
    qkv.outp = nullptr;
    gemm_tf32<<<dim3(4, 32, 3), 256, GNST * GSTAGE>>>(qkv);

    cudaStreamWaitEvent(0, evProbs, 0);
    attn_tf32<<<dim3(BB * HH, LL / 128), 256, 4 * ASTG>>>(pmask);

    GArgs og;
    og.A[0] = nullptr; og.A[1] = nullptr; og.A[2] = nullptr;
    og.Bi[0] = bo; og.Bi[1] = bo; og.Bi[2] = bo;
    og.sc[0] = 1.f; og.sc[1] = 1.f; og.sc[2] = 1.f;
    og.md[0] = 3; og.md[1] = 3; og.md[2] = 3;
    og.ws[0] = 3; og.ws[1] = 3; og.ws[2] = 3;
    og.outp = outp;
    gemm_tf32<<<dim3(4, 32, 1), 256, GNST * GSTAGE>>>(og);

    cudaStreamWaitEvent(0, evStats, 0);
    finalize_kernel<<<1, 32>>>(outp, out_size);
}

// round 13
// speedup vs baseline: 1.0561x; 1.0561x over previous
#include <cuda_runtime.h>
#include <cuda_fp16.h>
#include <math.h>
#include <stdint.h>

#define BB 4
#define LL 1024
#define DMODEL 512
#define HH 8
#define NC 8
#define DK 64
#define LOG_AV (-4.605170185988091f)   // log(0.01)

// ---------------- scratch (device globals: no allocation allowed) ----------
__device__ __align__(256) float g_probs[2][BB][HH][LL][NC]; // 0=q,1=k
__device__ __align__(256) uint4 g_qf[BB][HH][64][8][32];
__device__ __align__(256) uint4 g_kf[BB][HH][128][4][32];
__device__ __align__(256) uint4 g_vf[BB][HH][64][8][32];
__device__ __align__(256) uint4 g_wf[4][64][32][32];
// Pk B-fragments, hi/lo tf32 split: [n8 block][lane]{b0hi,b1hi,b0lo,b1lo}
__device__ __align__(256) uint4 g_pkf[BB][HH][128][32];
__device__ __align__(256) float g_ctx[BB][LL][DMODEL];
__device__ float g_M[2][BB][HH][36];
__device__ float g_klsum[2][BB][HH];
__device__ float g_dq2[2][BB][HH];
__device__ float g_dm1[2][BB][HH];

// ---------------- helpers ---------------------------------------------------
__device__ __forceinline__ uint32_t f2tf(float x) {
    uint32_t r;
    asm("cvt.rna.tf32.f32 %0, %1;" : "=r"(r) : "f"(x));
    return r;
}
__device__ __forceinline__ void mma8(float* c, const uint32_t* a, uint32_t b0, uint32_t b1) {
    asm volatile(
        "mma.sync.aligned.m16n8k8.row.col.f32.tf32.tf32.f32 "
        "{%0,%1,%2,%3}, {%4,%5,%6,%7}, {%8,%9}, {%0,%1,%2,%3};"
        : "+f"(c[0]), "+f"(c[1]), "+f"(c[2]), "+f"(c[3])
        : "r"(a[0]), "r"(a[1]), "r"(a[2]), "r"(a[3]), "r"(b0), "r"(b1));
}
__device__ __forceinline__ void ldm4(uint32_t* r, uint32_t saddr) {
    asm volatile("ldmatrix.sync.aligned.m8n8.x4.shared.b16 {%0,%1,%2,%3}, [%4];"
        : "=r"(r[0]), "=r"(r[1]), "=r"(r[2]), "=r"(r[3]) : "r"(saddr));
}
__device__ __forceinline__ void cp16(uint32_t saddr, const void* gptr) {
    asm volatile("cp.async.cg.shared.global [%0], [%1], 16;" :: "r"(saddr), "l"(gptr));
}
__device__ __forceinline__ void cp_commit() { asm volatile("cp.async.commit_group;"); }
template<int N> __device__ __forceinline__ void cp_wait() {
    asm volatile("cp.async.wait_group %0;" :: "n"(N));
}

// ---------------- zero accumulators ----------------------------------------
__global__ void zero_kernel() {
    int i = threadIdx.x;
    float* pM = &g_M[0][0][0][0];
    for (int e = i; e < 2 * BB * HH * 36; e += 256) pM[e] = 0.f;
    float* pk = &g_klsum[0][0][0];
    float* pd = &g_dq2[0][0][0];
    float* pm = &g_dm1[0][0][0];
    for (int e = i; e < 2 * BB * HH; e += 256) { pk[e] = 0.f; pd[e] = 0.f; pm[e] = 0.f; }
}

// ---------------- weight pack v2 --------------------------------------------
struct PArgs { const float* W[4]; };
__global__ __launch_bounds__(256) void pack_w(PArgs pa) {
    int idx = blockIdx.x * 256 + threadIdx.x;   // 65536
    int g = idx & 7;
    int k16 = (idx >> 3) & 31;
    int n8 = (idx >> 8) & 63;
    int w = idx >> 14;
    const float* src = pa.W[w] + (size_t)(n8 * 8 + g) * 512 + k16 * 16;
    float4 v0 = *(const float4*)(src);
    float4 v1 = *(const float4*)(src + 4);
    float4 v2 = *(const float4*)(src + 8);
    float4 v3 = *(const float4*)(src + 12);
    float c0[4] = { v0.x, v0.y, v0.z, v0.w };
    float c1[4] = { v1.x, v1.y, v1.z, v1.w };
    float c2[4] = { v2.x, v2.y, v2.z, v2.w };
    float c3[4] = { v3.x, v3.y, v3.z, v3.w };
#pragma unroll
    for (int q = 0; q < 4; q++) {
        uint4 o;
        o.x = f2tf(c0[q]); o.y = f2tf(c1[q]); o.z = f2tf(c2[q]); o.w = f2tf(c3[q]);
        g_wf[w][n8][k16][g * 4 + q] = o;
    }
}

// ---------------- pack Pk into hi/lo tf32 B-fragments -----------------------
__global__ __launch_bounds__(256) void pack_pk() {
    int idx = blockIdx.x * 256 + threadIdx.x;   // 131072
    int lane = idx & 31;
    int n8 = (idx >> 5) & 127;
    int h = (idx >> 12) & 7;
    int b = idx >> 15;
    int g = lane >> 2, q = lane & 3;
    int key = n8 * 8 + g;
    float v0 = g_probs[1][b][h][key][q];
    float v1 = g_probs[1][b][h][key][q + 4];
    uint32_t h0 = f2tf(v0), h1 = f2tf(v1);
    uint32_t l0 = f2tf(v0 - __uint_as_float(h0));
    uint32_t l1 = f2tf(v1 - __uint_as_float(h1));
    g_pkf[b][h][n8][lane] = make_uint4(h0, h1, l0, l1);
}

// ---------------- clustering: probs + kl only -------------------------------
__global__ __launch_bounds__(256) void clustering_kernel(
    const float* __restrict__ qin, const float* __restrict__ kin,
    const float* __restrict__ mu, const float* __restrict__ logvar,
    const float* __restrict__ logprior)
{
    __shared__ float4 mu4[NC][16];
    __shared__ float4 iv4[NC][16];
    __shared__ float lvs_s[NC], ratio_s[NC], logp_s[NC], prior_s[NC];

    int bx = blockIdx.x;
    int s = bx >> 5;
    int rem = bx & 31;
    int b = rem >> 3;
    int h = rem & 7;
    int tid = threadIdx.x;
    int l = blockIdx.y * 256 + tid;

    if (tid < NC * 16) {
        int c = tid >> 4, d4 = tid & 15;
        const float* msrc = &mu[(h * NC + c) * DK + d4 * 4];
        const float* lsrc = &logvar[(h * NC + c) * DK + d4 * 4];
        float4 mv = make_float4(msrc[0], msrc[1], msrc[2], msrc[3]);
        float4 ivv = make_float4(expf(-lsrc[0]), expf(-lsrc[1]), expf(-lsrc[2]), expf(-lsrc[3]));
        mu4[c][d4] = mv;
        iv4[c][d4] = ivv;
    }
    __syncthreads();
    if (tid < NC) {
        float ls = 0.f, rs = 0.f;
        const float avar = expf(LOG_AV);
        for (int d4 = 0; d4 < 16; d4++) {
            float4 ivv = iv4[tid][d4];
            rs += ivv.x + ivv.y + ivv.z + ivv.w;
        }
        for (int d = 0; d < DK; d++)
            ls += logvar[(h * NC + tid) * DK + d];
        lvs_s[tid] = ls;
        ratio_s[tid] = avar * rs;
    }
    if (tid == 0) {
        float mx = -1e30f;
        for (int c = 0; c < NC; c++) mx = fmaxf(mx, logprior[h * NC + c]);
        float ss = 0.f;
        for (int c = 0; c < NC; c++) ss += expf(logprior[h * NC + c] - mx);
        float lse = mx + logf(ss);
        for (int c = 0; c < NC; c++) {
            logp_s[c] = logprior[h * NC + c] - lse;
            prior_s[c] = expf(logp_s[c]);
        }
    }
    __syncthreads();

    const float* src = (s == 0) ? qin : kin;
    const float4* xr4 = (const float4*)(src + ((size_t)b * LL + l) * DMODEL + h * DK);

    float4 x4[16];
#pragma unroll
    for (int dd = 0; dd < 16; dd++) x4[dd] = xr4[dd];

    float mse[NC], logit[NC];
#pragma unroll
    for (int c = 0; c < NC; c++) {
        float a = 0.f;
#pragma unroll
        for (int d4 = 0; d4 < 16; d4++) {
            float4 mv = mu4[c][d4];
            float4 ivv = iv4[c][d4];
            float t0 = x4[d4].x - mv.x; a = fmaf(t0 * t0, ivv.x, a);
            float t1 = x4[d4].y - mv.y; a = fmaf(t1 * t1, ivv.y, a);
            float t2 = x4[d4].z - mv.z; a = fmaf(t2 * t2, ivv.z, a);
            float t3 = x4[d4].w - mv.w; a = fmaf(t3 * t3, ivv.w, a);
        }
        mse[c] = a;
        logit[c] = -0.5f * a - 0.5f * lvs_s[c] + logp_s[c];
    }
    float m = logit[0];
#pragma unroll
    for (int c = 1; c < NC; c++) m = fmaxf(m, logit[c]);
    float p[NC];
    float Zl = 0.f;
#pragma unroll
    for (int c = 0; c < NC; c++) { p[c] = expf(logit[c] - m); Zl += p[c]; }
    float lz = logf(Zl);
    float inv = 1.f / Zl;

    float t1 = 0.f;
#pragma unroll
    for (int c = 0; c < NC; c++)
        t1 += prior_s[c] * (logp_s[c] - (logit[c] - m - lz));
#pragma unroll
    for (int c = 0; c < NC; c++) p[c] *= inv;
    float t2 = 0.f;
#pragma unroll
    for (int c = 0; c < NC; c++)
        t2 += p[c] * (mse[c] + ratio_s[c] + lvs_s[c]);
    float klloc = t1 + 0.5f * t2;

#pragma unroll
    for (int c = 0; c < NC; c++) g_probs[s][b][h][l][c] = p[c];

    float v = klloc;
    v += __shfl_xor_sync(0xffffffffu, v, 16);
    v += __shfl_xor_sync(0xffffffffu, v, 8);
    v += __shfl_xor_sync(0xffffffffu, v, 4);
    v += __shfl_xor_sync(0xffffffffu, v, 2);
    v += __shfl_xor_sync(0xffffffffu, v, 1);
    if ((tid & 31) == 0) atomicAdd(&g_klsum[s][b][h], v);
}

// ---------------- stats: M = P^T P upper-tri, dq2, dm1 ----------------------
__global__ __launch_bounds__(256) void stats_kernel()
{
    int sbh = blockIdx.x >> 2;
    int chunk = blockIdx.x & 3;
    int s = sbh >> 5, b = (sbh >> 3) & 3, h = sbh & 7;
    int tid = threadIdx.x;
    int l = chunk * 256 + tid;

    float4 pA = *(const float4*)&g_probs[s][b][h][l][0];
    float4 pB = *(const float4*)&g_probs[s][b][h][l][4];
    float p[8] = { pA.x, pA.y, pA.z, pA.w, pB.x, pB.y, pB.z, pB.w };
    float dq = 0.f;
#pragma unroll
    for (int c = 0; c < 8; c++) dq = fmaf(p[c], p[c], dq);
    float dq2 = dq * dq;
    float dm1 = (dq - 1.f) * (dq - 1.f);
    float M[36];
    {
        int e = 0;
#pragma unroll
        for (int c = 0; c < 8; c++)
#pragma unroll
            for (int c2 = c; c2 < 8; c2++) M[e++] = p[c] * p[c2];
    }

#pragma unroll
    for (int e = 0; e < 36; e++) {
        float v = M[e];
        v += __shfl_xor_sync(0xffffffffu, v, 16);
        v += __shfl_xor_sync(0xffffffffu, v, 8);
        v += __shfl_xor_sync(0xffffffffu, v, 4);
        v += __shfl_xor_sync(0xffffffffu, v, 2);
        v += __shfl_xor_sync(0xffffffffu, v, 1);
        if ((tid & 31) == 0) atomicAdd(&g_M[s][b][h][e], v);
    }
    float v2[2] = { dq2, dm1 };
    float* d2[2] = { &g_dq2[s][b][h], &g_dm1[s][b][h] };
#pragma unroll
    for (int e = 0; e < 2; e++) {
        float v = v2[e];
        v += __shfl_xor_sync(0xffffffffu, v, 16);
        v += __shfl_xor_sync(0xffffffffu, v, 8);
        v += __shfl_xor_sync(0xffffffffu, v, 4);
        v += __shfl_xor_sync(0xffffffffu, v, 2);
        v += __shfl_xor_sync(0xffffffffu, v, 1);
        if ((tid & 31) == 0) atomicAdd(d2[e], v);
    }
}

// ---------------- cp.async 6-stage tf32 GEMM, ldmatrix A-feed ----------------
// A-operand fed as raw fp32 bits (HW truncates to tf32) — no cvt in mainloop.
#define GSTR 20
#define GSTAGE 18432
#define GNST 6
struct GArgs {
    const float* A[3];
    const float* Bi[3];
    float sc[3];
    int md[3];
    int ws[3];
    float* outp;
};

__global__ __launch_bounds__(256, 2) void gemm_tf32(GArgs ga)
{
    extern __shared__ uint8_t sm[];
    int z = blockIdx.z;
    const float* Ap = ga.A[z];
    if (!Ap) Ap = &g_ctx[0][0][0];
    const float* bias = ga.Bi[z];
    float scale = ga.sc[z];
    int out_mode = ga.md[z];
    int wsel = ga.ws[z];

    int tid = threadIdx.x;
    int lane = tid & 31, wid = tid >> 5;
    int g = lane >> 2, q = lane & 3;
    int wm = wid & 3, wn = wid >> 2;
    int m0 = blockIdx.y * 128, n0 = blockIdx.x * 128;
    int n8base = n0 >> 3;

    int lt = lane >> 3, lr = lane & 7;
    int ldrow = ((lt & 1) << 3) + lr;
    int ldcol = (lt & 2) << 1;

    auto issue = [&](int kc) {
        int stg = kc % GNST;
        uint32_t base = (uint32_t)__cvta_generic_to_shared(sm + stg * GSTAGE);
#pragma unroll
        for (int i = 0; i < 2; i++) {
            int cid = tid + 256 * i;
            int row = cid >> 2, c = cid & 3;
            cp16(base + (row * GSTR + c * 4) * 4,
                 Ap + (size_t)(m0 + row) * 512 + kc * 16 + c * 4);
            int n8b = cid >> 5, ln = cid & 31;
            cp16(base + 10240 + cid * 16, &g_wf[wsel][n8base + n8b][kc][ln]);
        }
        cp_commit();
    };

    float acc[2][8][4];
#pragma unroll
    for (int mt = 0; mt < 2; mt++)
#pragma unroll
        for (int nt = 0; nt < 8; nt++)
#pragma unroll
            for (int s = 0; s < 4; s++) acc[mt][nt][s] = 0.f;

    issue(0); issue(1); issue(2);

    for (int it = 0; it < 16; it++) {
        if (it == 15) cp_wait<0>(); else cp_wait<1>();
        __syncthreads();
        int c3 = 2 * it + 3, c4 = 2 * it + 4;
        if (c3 < 32) issue(c3);
        if (c4 < 32) issue(c4);

        for (int half = 0; half < 2; half++) {
            int kc = 2 * it + half;
            uint32_t As_s = (uint32_t)__cvta_generic_to_shared(sm + (kc % GNST) * GSTAGE);
            const uint4* Bsm = (const uint4*)(sm + (kc % GNST) * GSTAGE + 10240);

            uint4 bfr[8];
#pragma unroll
            for (int nt = 0; nt < 8; nt++)
                bfr[nt] = Bsm[(wn * 8 + nt) * 32 + lane];

#pragma unroll
            for (int ks = 0; ks < 2; ks++) {
                uint32_t a[2][4];
#pragma unroll
                for (int mt = 0; mt < 2; mt++) {
                    int mr = wm * 32 + mt * 16;
                    ldm4(a[mt], As_s + ((mr + ldrow) * GSTR + ks * 8 + ldcol) * 4);
                }
#pragma unroll
                for (int nt = 0; nt < 8; nt++) {
                    uint32_t b0 = ks ? bfr[nt].z : bfr[nt].x;
                    uint32_t b1 = ks ? bfr[nt].w : bfr[nt].y;
                    mma8(acc[0][nt], a[0], b0, b1);
                    mma8(acc[1][nt], a[1], b0, b1);
                }
            }
        }
    }

    // ---------- staged epilogue: smem transpose -> coalesced STG.128 -------
    __syncthreads();
    float* S = (float*)sm + wid * 1088;
    int C0 = n0 + wn * 64;
    int hh = C0 >> 6;

#pragma unroll
    for (int mt = 0; mt < 2; mt++) {
        if (mt) __syncwarp();
#pragma unroll
        for (int nt = 0; nt < 8; nt++)
#pragma unroll
            for (int s = 0; s < 4; s++) {
                int r = g + ((s >= 2) ? 8 : 0);
                int ct = nt * 8 + 2 * q + (s & 1);
                S[r * 68 + ct] = (acc[mt][nt][s] + bias[C0 + ct]) * scale;
            }
        __syncwarp();

        int R0 = m0 + wm * 32 + mt * 16;
        if (out_mode == 3) {
#pragma unroll
            for (int it = 0; it < 8; it++) {
                int linear = it * 32 + lane;
                int row = linear >> 4, f4 = linear & 15;
                float4 v = *(const float4*)&S[row * 68 + f4 * 4];
                *(float4*)&ga.outp[(size_t)(R0 + row) * 512 + C0 + f4 * 4] = v;
            }
        } else {
            int bb = R0 >> 10;
            int l0 = R0 & 1023;
            if (out_mode == 0) {
                int l16 = l0 >> 4;
#pragma unroll
                for (int ks = 0; ks < 8; ks++) {
                    uint4 v;
                    v.x = f2tf(S[g * 68 + ks * 8 + q]);
                    v.y = f2tf(S[(g + 8) * 68 + ks * 8 + q]);
                    v.z = f2tf(S[g * 68 + ks * 8 + q + 4]);
                    v.w = f2tf(S[(g + 8) * 68 + ks * 8 + q + 4]);
                    g_qf[bb][hh][l16][ks][lane] = v;
                }
            } else if (out_mode == 1) {
#pragma unroll
                for (int j = 0; j < 2; j++)
#pragma unroll
                    for (int k16 = 0; k16 < 4; k16++) {
                        int rr = j * 8 + g;
                        uint4 v;
                        v.x = f2tf(S[rr * 68 + k16 * 16 + q]);
                        v.y = f2tf(S[rr * 68 + k16 * 16 + q + 4]);
                        v.z = f2tf(S[rr * 68 + k16 * 16 + q + 8]);
                        v.w = f2tf(S[rr * 68 + k16 * 16 + q + 12]);
                        g_kf[bb][hh][(l0 >> 3) + j][k16][lane] = v;
                    }
            } else {
                int k16v = l0 >> 4;
#pragma unroll
                for (int d8 = 0; d8 < 8; d8++) {
                    uint4 v;
                    v.x = f2tf(S[q * 68 + d8 * 8 + g]);
                    v.y = f2tf(S[(q + 4) * 68 + d8 * 8 + g]);
                    v.z = f2tf(S[(q + 8) * 68 + d8 * 8 + g]);
                    v.w = f2tf(S[(q + 12) * 68 + d8 * 8 + g]);
                    g_vf[bb][hh][k16v][d8][lane] = v;
                }
            }
        }
    }
}

// ---------------- fused flash attention: 256 thr, 128 q-rows, 3-stage --------
#define ASTG 37120

__global__ __launch_bounds__(256) void attn_tf32(const float* __restrict__ pm)
{
    extern __shared__ uint8_t sm[];

    int bh = blockIdx.x;
    int b = bh >> 3, h = bh & 7;
    int tid = threadIdx.x;
    int lane = tid & 31, w = tid >> 5;
    int g = lane >> 2, q = lane & 3;
    int q0 = blockIdx.y * 128;
    int r0 = q0 + w * 16 + g;
    int r1 = r0 + 8;

    auto issue = [&](int t, int stg) {
        uint32_t base = (uint32_t)__cvta_generic_to_shared(sm + stg * ASTG);
        const uint4* kg_ = &g_kf[b][h][t * 8][0][0];
        const uint4* vg_ = &g_vf[b][h][t * 4][0][0];
#pragma unroll
        for (int i = 0; i < 4; i++) {
            int cid = tid + 256 * i;
            cp16(base + cid * 16, kg_ + cid);
            cp16(base + 16384 + cid * 16, vg_ + cid);
        }
        cp16(base + 32768 + tid * 16, &g_pkf[b][h][t * 8][0] + tid);
        if (tid < 16)
            cp16(base + 36864 + tid * 16, pm + (size_t)b * LL + t * 64 + tid * 4);
        cp_commit();
    };

    uint32_t qa[8][4];
    {
        int l16 = blockIdx.y * 8 + w;
#pragma unroll
        for (int ks = 0; ks < 8; ks++) {
            uint4 t0 = g_qf[b][h][l16][ks][lane];
            qa[ks][0] = t0.x; qa[ks][1] = t0.y; qa[ks][2] = t0.z; qa[ks][3] = t0.w;
        }
    }
    // Pq A-fragments, exact hi/lo tf32 split (constant across tiles)
    uint32_t ahi[4], alo[4];
    {
        float p00 = g_probs[0][b][h][r0][q];
        float p10 = g_probs[0][b][h][r1][q];
        float p04 = g_probs[0][b][h][r0][q + 4];
        float p14 = g_probs[0][b][h][r1][q + 4];
        ahi[0] = f2tf(p00); alo[0] = f2tf(p00 - __uint_as_float(ahi[0]));
        ahi[1] = f2tf(p10); alo[1] = f2tf(p10 - __uint_as_float(ahi[1]));
        ahi[2] = f2tf(p04); alo[2] = f2tf(p04 - __uint_as_float(ahi[2]));
        ahi[3] = f2tf(p14); alo[3] = f2tf(p14 - __uint_as_float(ahi[3]));
    }

    float accO[8][4];
#pragma unroll
    for (int nt = 0; nt < 8; nt++)
#pragma unroll
        for (int s = 0; s < 4; s++) accO[nt][s] = 0.f;
    float mrow0 = -1e30f, mrow1 = -1e30f, Z0 = 0.f, Z1 = 0.f;

    issue(0, 0);
    issue(1, 1);

    for (int t = 0; t < 16; t++) {
        if (t == 15) cp_wait<0>(); else cp_wait<1>();
        __syncthreads();
        if (t + 2 < 16) issue(t + 2, (t + 2) % 3);

        int stg = t % 3;
        const uint4* Ksm = (const uint4*)(sm + stg * ASTG);
        const uint4* Vsm = (const uint4*)(sm + stg * ASTG + 16384);
        const uint4* Pkf = (const uint4*)(sm + stg * ASTG + 32768);
        const float* padk = (const float*)(sm + stg * ASTG + 36864);

        // sim = Pq·Pk^T on the tensor pipe, exact 4-term hi/lo split
        float accS[8][4];
#pragma unroll
        for (int nt = 0; nt < 8; nt++)
#pragma unroll
            for (int s = 0; s < 4; s++) accS[nt][s] = 0.f;
#pragma unroll
        for (int nt = 0; nt < 8; nt++) {
            uint4 pk = Pkf[nt * 32 + lane];
            mma8(accS[nt], ahi, pk.x, pk.y);
            mma8(accS[nt], alo, pk.x, pk.y);
            mma8(accS[nt], ahi, pk.z, pk.w);
            mma8(accS[nt], alo, pk.z, pk.w);
        }

        // sim -> bias = -10000*cmask ; u = 1-cm packed to half2
        __half2 uh0[8], uh1[8];
#pragma unroll
        for (int nt = 0; nt < 8; nt++) {
            float2 pd = *(const float2*)&padk[nt * 8 + 2 * q];
            float cm0 = fminf(fmaxf(1.f - accS[nt][0] + pd.x, 0.f), 1.f);
            float cm1 = fminf(fmaxf(1.f - accS[nt][1] + pd.y, 0.f), 1.f);
            float cm2 = fminf(fmaxf(1.f - accS[nt][2] + pd.x, 0.f), 1.f);
            float cm3 = fminf(fmaxf(1.f - accS[nt][3] + pd.y, 0.f), 1.f);
            accS[nt][0] = -10000.f * cm0;
            accS[nt][1] = -10000.f * cm1;
            accS[nt][2] = -10000.f * cm2;
            accS[nt][3] = -10000.f * cm3;
            uh0[nt] = __floats2half2_rn(1.f - cm0, 1.f - cm1);
            uh1[nt] = __floats2half2_rn(1.f - cm2, 1.f - cm3);
        }

        // S += Q * K^T
#pragma unroll
        for (int ks2 = 0; ks2 < 4; ks2++) {
#pragma unroll
            for (int nt = 0; nt < 8; nt++) {
                uint4 kb = Ksm[(nt * 4 + ks2) * 32 + lane];
                mma8(accS[nt], qa[2 * ks2], kb.x, kb.y);
                mma8(accS[nt], qa[2 * ks2 + 1], kb.z, kb.w);
            }
        }

        // online softmax
        float t0 = accS[0][0], t1v = accS[0][2];
#pragma unroll
        for (int nt = 0; nt < 8; nt++) {
            t0 = fmaxf(t0, fmaxf(accS[nt][0], accS[nt][1]));
            t1v = fmaxf(t1v, fmaxf(accS[nt][2], accS[nt][3]));
        }
        t0 = fmaxf(t0, __shfl_xor_sync(0xffffffffu, t0, 1));
        t0 = fmaxf(t0, __shfl_xor_sync(0xffffffffu, t0, 2));
        t1v = fmaxf(t1v, __shfl_xor_sync(0xffffffffu, t1v, 1));
        t1v = fmaxf(t1v, __shfl_xor_sync(0xffffffffu, t1v, 2));
        float mn0 = fmaxf(mrow0, t0), mn1 = fmaxf(mrow1, t1v);
        float corr0 = __expf(mrow0 - mn0), corr1 = __expf(mrow1 - mn1);
        mrow0 = mn0; mrow1 = mn1;
        Z0 *= corr0; Z1 *= corr1;
#pragma unroll
        for (int nt = 0; nt < 8; nt++) {
            accO[nt][0] *= corr0; accO[nt][1] *= corr0;
            accO[nt][2] *= corr1; accO[nt][3] *= corr1;
        }
        float z0 = 0.f, z1 = 0.f;
#pragma unroll
        for (int nt = 0; nt < 8; nt++) {
            float e0 = __expf(accS[nt][0] - mn0);
            float e1 = __expf(accS[nt][1] - mn0);
            float e2 = __expf(accS[nt][2] - mn1);
            float e3 = __expf(accS[nt][3] - mn1);
            z0 += e0 + e1; z1 += e2 + e3;
            float2 u0 = __half22float2(uh0[nt]);
            float2 u1 = __half22float2(uh1[nt]);
            accS[nt][0] = e0 * u0.x;
            accS[nt][1] = e1 * u0.y;
            accS[nt][2] = e2 * u1.x;
            accS[nt][3] = e3 * u1.y;
        }
        Z0 += z0; Z1 += z1;

        // O += P * V : permute C-frag -> A-frag via quad shuffles
        int srcA = (lane & ~3) | (q >> 1);
        int srcB = srcA + 2;
        bool odd = (q & 1);
#pragma unroll
        for (int kg2 = 0; kg2 < 4; kg2++) {
            uint32_t aP[2][4];
#pragma unroll
            for (int half = 0; half < 2; half++) {
                int kg = 2 * kg2 + half;
                float x0 = __shfl_sync(0xffffffffu, accS[kg][0], srcA);
                float x1 = __shfl_sync(0xffffffffu, accS[kg][1], srcA);
                float x4 = __shfl_sync(0xffffffffu, accS[kg][0], srcB);
                float x5 = __shfl_sync(0xffffffffu, accS[kg][1], srcB);
                float y0 = __shfl_sync(0xffffffffu, accS[kg][2], srcA);
                float y1 = __shfl_sync(0xffffffffu, accS[kg][3], srcA);
                float y4 = __shfl_sync(0xffffffffu, accS[kg][2], srcB);
                float y5 = __shfl_sync(0xffffffffu, accS[kg][3], srcB);
                aP[half][0] = f2tf(odd ? x1 : x0);
                aP[half][1] = f2tf(odd ? y1 : y0);
                aP[half][2] = f2tf(odd ? x5 : x4);
                aP[half][3] = f2tf(odd ? y5 : y4);
            }
#pragma unroll
            for (int nt = 0; nt < 8; nt++) {
                uint4 vb = Vsm[(kg2 * 8 + nt) * 32 + lane];
                mma8(accO[nt], aP[0], vb.x, vb.y);
                mma8(accO[nt], aP[1], vb.z, vb.w);
            }
        }
    }

    Z0 += __shfl_xor_sync(0xffffffffu, Z0, 1);
    Z0 += __shfl_xor_sync(0xffffffffu, Z0, 2);
    Z1 += __shfl_xor_sync(0xffffffffu, Z1, 1);
    Z1 += __shfl_xor_sync(0xffffffffu, Z1, 2);
    float iz0 = 1.f / Z0, iz1 = 1.f / Z1;
#pragma unroll
    for (int nt = 0; nt < 8; nt++) {
        float2 o0 = make_float2(accO[nt][0] * iz0, accO[nt][1] * iz0);
        float2 o1 = make_float2(accO[nt][2] * iz1, accO[nt][3] * iz1);
        *(float2*)&g_ctx[b][r0][h * DK + nt * 8 + 2 * q] = o0;
        *(float2*)&g_ctx[b][r1][h * DK + nt * 8 + 2 * q] = o1;
    }
}

// ---------------- finalize ---------------------------------------------------
__global__ void finalize_kernel(float* __restrict__ out, int out_size)
{
    int b = threadIdx.x;
    if (b >= BB) return;
    float kl = 0.f;
    for (int s = 0; s < 2; s++)
        for (int h = 0; h < HH; h++) kl += g_klsum[s][b][h];
    const float c3 = -0.5f * (1.0f + LOG_AV) * (float)DK;
    float kl_total = kl / (float)(HH * LL) + 2.f * c3;

    float dv = 0.f;
    for (int s = 0; s < 2; s++)
        for (int h = 0; h < HH; h++) {
            float frob = 0.f;
            int e = 0;
            for (int c = 0; c < NC; c++)
                for (int c2 = c; c2 < NC; c2++) {
                    float mv = g_M[s][b][h][e++];
                    frob += (c2 == c) ? mv * mv : 2.f * mv * mv;
                }
            dv += 0.75f * (frob - g_dq2[s][b][h]) + 1.25f * g_dm1[s][b][h];
        }
    dv /= (float)HH * (float)LL * (float)LL;

    long base = (long)BB * LL * DMODEL;
    if (out_size >= base + 2 * BB) {
        out[base + b] = kl_total;
        out[base + BB + b] = dv;
    }
}

// ---------------- launch -----------------------------------------------------
extern "C" void kernel_launch(void* const* d_in, const int* in_sizes, int n_in,
                              void* d_out, int out_size)
{
    const float* query  = (const float*)d_in[0];
    const float* key    = (const float*)d_in[1];
    const float* value  = (const float*)d_in[2];
    const float* pmask  = (const float*)d_in[3];
    const float* Wq = (const float*)d_in[4];
    const float* bq = (const float*)d_in[5];
    const float* Wk = (const float*)d_in[6];
    const float* bk = (const float*)d_in[7];
    const float* Wv = (const float*)d_in[8];
    const float* bv = (const float*)d_in[9];
    const float* Wo = (const float*)d_in[10];
    const float* bo = (const float*)d_in[11];
    const float* tok_mu = (const float*)d_in[12];
    const float* tok_lv = (const float*)d_in[13];
    const float* tok_lp = (const float*)d_in[14];
    float* outp = (float*)d_out;

    cudaFuncSetAttribute(gemm_tf32, cudaFuncAttributeMaxDynamicSharedMemorySize, GNST * GSTAGE);
    cudaFuncSetAttribute(attn_tf32, cudaFuncAttributeMaxDynamicSharedMemorySize, 3 * ASTG);

    cudaStream_t sB;
    cudaStreamCreateWithFlags(&sB, cudaStreamNonBlocking);
    cudaEvent_t evFork, evProbs, evStats;
    cudaEventCreateWithFlags(&evFork, cudaEventDisableTiming);
    cudaEventCreateWithFlags(&evProbs, cudaEventDisableTiming);
    cudaEventCreateWithFlags(&evStats, cudaEventDisableTiming);

    cudaEventRecord(evFork, 0);
    cudaStreamWaitEvent(sB, evFork, 0);

    // branch B: zero -> clustering -> pack_pk -> (evProbs) -> stats -> (evStats)
    zero_kernel<<<1, 256, 0, sB>>>();
    clustering_kernel<<<dim3(2 * BB * HH, 4), 256, 0, sB>>>(query, key, tok_mu, tok_lv, tok_lp);
    pack_pk<<<512, 256, 0, sB>>>();
    cudaEventRecord(evProbs, sB);
    stats_kernel<<<256, 256, 0, sB>>>();
    cudaEventRecord(evStats, sB);

    // branch A: pack_w -> QKV gemm
    PArgs pw;
    pw.W[0] = Wq; pw.W[1] = Wk; pw.W[2] = Wv; pw.W[3] = Wo;
    pack_w<<<256, 256>>>(pw);

    GArgs qkv;
    qkv.A[0] = query; qkv.A[1] = key; qkv.A[2] = value;
    qkv.Bi[0] = bq;   qkv.Bi[1] = bk; qkv.Bi[2] = bv;
    qkv.sc[0] = 0.125f; qkv.sc[1] = 1.f; qkv.sc[2] = 1.f;
    qkv.md[0] = 0; qkv.md[1] = 1; qkv.md[2] = 2;
    qkv.ws[0] = 0; qkv.ws[1] = 1; qkv.ws[2] = 2;
    qkv.outp = nullptr;
    gemm_tf32<<<dim3(4, 32, 3), 256, GNST * GSTAGE>>>(qkv);

    cudaStreamWaitEvent(0, evProbs, 0);
    attn_tf32<<<dim3(BB * HH, LL / 128), 256, 3 * ASTG>>>(pmask);

    GArgs og;
    og.A[0] = nullptr; og.A[1] = nullptr; og.A[2] = nullptr;
    og.Bi[0] = bo; og.Bi[1] = bo; og.Bi[2] = bo;
    og.sc[0] = 1.f; og.sc[1] = 1.f; og.sc[2] = 1.f;
    og.md[0] = 3; og.md[1] = 3; og.md[2] = 3;
    og.ws[0] = 3; og.ws[1] = 3; og.ws[2] = 3;
    og.outp = outp;
    gemm_tf32<<<dim3(4, 32, 1), 256, GNST * GSTAGE>>>(og);

    cudaStreamWaitEvent(0, evStats, 0);
    finalize_kernel<<<1, 32>>>(outp, out_size);
}

// round 15
// speedup vs baseline: 1.0594x; 1.0031x over previous
#include <cuda_runtime.h>
#include <cuda_fp16.h>
#include <math.h>
#include <stdint.h>

#define BB 4
#define LL 1024
#define DMODEL 512
#define HH 8
#define NC 8
#define DK 64
#define LOG_AV (-4.605170185988091f)   // log(0.01)

// ---------------- scratch (device globals: no allocation allowed) ----------
__device__ __align__(256) float g_probs[2][BB][HH][LL][NC]; // 0=q,1=k
__device__ __align__(256) uint4 g_qf[BB][HH][64][8][32];
__device__ __align__(256) uint4 g_kf[BB][HH][128][4][32];
__device__ __align__(256) uint4 g_vf[BB][HH][64][8][32];
__device__ __align__(256) uint4 g_wf[4][64][32][32];
// Pk B-fragments, hi/lo tf32 split: [n8 block][lane]{b0hi,b1hi,b0lo,b1lo}
__device__ __align__(256) uint4 g_pkf[BB][HH][128][32];
__device__ __align__(256) float g_ctx[BB][LL][DMODEL];
__device__ float g_M[2][BB][HH][36];
__device__ float g_klsum[2][BB][HH];
__device__ float g_dq2[2][BB][HH];
__device__ float g_dm1[2][BB][HH];

// ---------------- helpers ---------------------------------------------------
__device__ __forceinline__ uint32_t f2tf(float x) {
    uint32_t r;
    asm("cvt.rna.tf32.f32 %0, %1;" : "=r"(r) : "f"(x));
    return r;
}
__device__ __forceinline__ void mma8(float* c, const uint32_t* a, uint32_t b0, uint32_t b1) {
    asm volatile(
        "mma.sync.aligned.m16n8k8.row.col.f32.tf32.tf32.f32 "
        "{%0,%1,%2,%3}, {%4,%5,%6,%7}, {%8,%9}, {%0,%1,%2,%3};"
        : "+f"(c[0]), "+f"(c[1]), "+f"(c[2]), "+f"(c[3])
        : "r"(a[0]), "r"(a[1]), "r"(a[2]), "r"(a[3]), "r"(b0), "r"(b1));
}
__device__ __forceinline__ void ldm4(uint32_t* r, uint32_t saddr) {
    asm volatile("ldmatrix.sync.aligned.m8n8.x4.shared.b16 {%0,%1,%2,%3}, [%4];"
        : "=r"(r[0]), "=r"(r[1]), "=r"(r[2]), "=r"(r[3]) : "r"(saddr));
}
__device__ __forceinline__ void cp16(uint32_t saddr, const void* gptr) {
    asm volatile("cp.async.cg.shared.global [%0], [%1], 16;" :: "r"(saddr), "l"(gptr));
}
__device__ __forceinline__ void cp_commit() { asm volatile("cp.async.commit_group;"); }
template<int N> __device__ __forceinline__ void cp_wait() {
    asm volatile("cp.async.wait_group %0;" :: "n"(N));
}

// ---------------- zero accumulators ----------------------------------------
__global__ void zero_kernel() {
    int i = threadIdx.x;
    float* pM = &g_M[0][0][0][0];
    for (int e = i; e < 2 * BB * HH * 36; e += 256) pM[e] = 0.f;
    float* pk = &g_klsum[0][0][0];
    float* pd = &g_dq2[0][0][0];
    float* pm = &g_dm1[0][0][0];
    for (int e = i; e < 2 * BB * HH; e += 256) { pk[e] = 0.f; pd[e] = 0.f; pm[e] = 0.f; }
}

// ---------------- weight pack v2 --------------------------------------------
struct PArgs { const float* W[4]; };
__global__ __launch_bounds__(256) void pack_w(PArgs pa) {
    int idx = blockIdx.x * 256 + threadIdx.x;   // 65536
    int g = idx & 7;
    int k16 = (idx >> 3) & 31;
    int n8 = (idx >> 8) & 63;
    int w = idx >> 14;
    const float* src = pa.W[w] + (size_t)(n8 * 8 + g) * 512 + k16 * 16;
    float4 v0 = *(const float4*)(src);
    float4 v1 = *(const float4*)(src + 4);
    float4 v2 = *(const float4*)(src + 8);
    float4 v3 = *(const float4*)(src + 12);
    float c0[4] = { v0.x, v0.y, v0.z, v0.w };
    float c1[4] = { v1.x, v1.y, v1.z, v1.w };
    float c2[4] = { v2.x, v2.y, v2.z, v2.w };
    float c3[4] = { v3.x, v3.y, v3.z, v3.w };
#pragma unroll
    for (int q = 0; q < 4; q++) {
        uint4 o;
        o.x = f2tf(c0[q]); o.y = f2tf(c1[q]); o.z = f2tf(c2[q]); o.w = f2tf(c3[q]);
        g_wf[w][n8][k16][g * 4 + q] = o;
    }
}

// ---------------- pack Pk into hi/lo tf32 B-fragments -----------------------
__global__ __launch_bounds__(256) void pack_pk() {
    int idx = blockIdx.x * 256 + threadIdx.x;   // 131072
    int lane = idx & 31;
    int n8 = (idx >> 5) & 127;
    int h = (idx >> 12) & 7;
    int b = idx >> 15;
    int g = lane >> 2, q = lane & 3;
    int key = n8 * 8 + g;
    float v0 = g_probs[1][b][h][key][q];
    float v1 = g_probs[1][b][h][key][q + 4];
    uint32_t h0 = f2tf(v0), h1 = f2tf(v1);
    uint32_t l0 = f2tf(v0 - __uint_as_float(h0));
    uint32_t l1 = f2tf(v1 - __uint_as_float(h1));
    g_pkf[b][h][n8][lane] = make_uint4(h0, h1, l0, l1);
}

// ---------------- clustering: probs + kl only -------------------------------
__global__ __launch_bounds__(256) void clustering_kernel(
    const float* __restrict__ qin, const float* __restrict__ kin,
    const float* __restrict__ mu, const float* __restrict__ logvar,
    const float* __restrict__ logprior)
{
    __shared__ float4 mu4[NC][16];
    __shared__ float4 iv4[NC][16];
    __shared__ float lvs_s[NC], ratio_s[NC], logp_s[NC], prior_s[NC];

    int bx = blockIdx.x;
    int s = bx >> 5;
    int rem = bx & 31;
    int b = rem >> 3;
    int h = rem & 7;
    int tid = threadIdx.x;
    int l = blockIdx.y * 256 + tid;

    if (tid < NC * 16) {
        int c = tid >> 4, d4 = tid & 15;
        const float* msrc = &mu[(h * NC + c) * DK + d4 * 4];
        const float* lsrc = &logvar[(h * NC + c) * DK + d4 * 4];
        float4 mv = make_float4(msrc[0], msrc[1], msrc[2], msrc[3]);
        float4 ivv = make_float4(expf(-lsrc[0]), expf(-lsrc[1]), expf(-lsrc[2]), expf(-lsrc[3]));
        mu4[c][d4] = mv;
        iv4[c][d4] = ivv;
    }
    __syncthreads();
    if (tid < NC) {
        float ls = 0.f, rs = 0.f;
        const float avar = expf(LOG_AV);
        for (int d4 = 0; d4 < 16; d4++) {
            float4 ivv = iv4[tid][d4];
            rs += ivv.x + ivv.y + ivv.z + ivv.w;
        }
        for (int d = 0; d < DK; d++)
            ls += logvar[(h * NC + tid) * DK + d];
        lvs_s[tid] = ls;
        ratio_s[tid] = avar * rs;
    }
    if (tid == 0) {
        float mx = -1e30f;
        for (int c = 0; c < NC; c++) mx = fmaxf(mx, logprior[h * NC + c]);
        float ss = 0.f;
        for (int c = 0; c < NC; c++) ss += expf(logprior[h * NC + c] - mx);
        float lse = mx + logf(ss);
        for (int c = 0; c < NC; c++) {
            logp_s[c] = logprior[h * NC + c] - lse;
            prior_s[c] = expf(logp_s[c]);
        }
    }
    __syncthreads();

    const float* src = (s == 0) ? qin : kin;
    const float4* xr4 = (const float4*)(src + ((size_t)b * LL + l) * DMODEL + h * DK);

    float4 x4[16];
#pragma unroll
    for (int dd = 0; dd < 16; dd++) x4[dd] = xr4[dd];

    float mse[NC], logit[NC];
#pragma unroll
    for (int c = 0; c < NC; c++) {
        float a = 0.f;
#pragma unroll
        for (int d4 = 0; d4 < 16; d4++) {
            float4 mv = mu4[c][d4];
            float4 ivv = iv4[c][d4];
            float t0 = x4[d4].x - mv.x; a = fmaf(t0 * t0, ivv.x, a);
            float t1 = x4[d4].y - mv.y; a = fmaf(t1 * t1, ivv.y, a);
            float t2 = x4[d4].z - mv.z; a = fmaf(t2 * t2, ivv.z, a);
            float t3 = x4[d4].w - mv.w; a = fmaf(t3 * t3, ivv.w, a);
        }
        mse[c] = a;
        logit[c] = -0.5f * a - 0.5f * lvs_s[c] + logp_s[c];
    }
    float m = logit[0];
#pragma unroll
    for (int c = 1; c < NC; c++) m = fmaxf(m, logit[c]);
    float p[NC];
    float Zl = 0.f;
#pragma unroll
    for (int c = 0; c < NC; c++) { p[c] = expf(logit[c] - m); Zl += p[c]; }
    float lz = logf(Zl);
    float inv = 1.f / Zl;

    float t1 = 0.f;
#pragma unroll
    for (int c = 0; c < NC; c++)
        t1 += prior_s[c] * (logp_s[c] - (logit[c] - m - lz));
#pragma unroll
    for (int c = 0; c < NC; c++) p[c] *= inv;
    float t2 = 0.f;
#pragma unroll
    for (int c = 0; c < NC; c++)
        t2 += p[c] * (mse[c] + ratio_s[c] + lvs_s[c]);
    float klloc = t1 + 0.5f * t2;

#pragma unroll
    for (int c = 0; c < NC; c++) g_probs[s][b][h][l][c] = p[c];

    float v = klloc;
    v += __shfl_xor_sync(0xffffffffu, v, 16);
    v += __shfl_xor_sync(0xffffffffu, v, 8);
    v += __shfl_xor_sync(0xffffffffu, v, 4);
    v += __shfl_xor_sync(0xffffffffu, v, 2);
    v += __shfl_xor_sync(0xffffffffu, v, 1);
    if ((tid & 31) == 0) atomicAdd(&g_klsum[s][b][h], v);
}

// ---------------- stats: M = P^T P upper-tri, dq2, dm1 ----------------------
__global__ __launch_bounds__(256) void stats_kernel()
{
    int sbh = blockIdx.x >> 2;
    int chunk = blockIdx.x & 3;
    int s = sbh >> 5, b = (sbh >> 3) & 3, h = sbh & 7;
    int tid = threadIdx.x;
    int l = chunk * 256 + tid;

    float4 pA = *(const float4*)&g_probs[s][b][h][l][0];
    float4 pB = *(const float4*)&g_probs[s][b][h][l][4];
    float p[8] = { pA.x, pA.y, pA.z, pA.w, pB.x, pB.y, pB.z, pB.w };
    float dq = 0.f;
#pragma unroll
    for (int c = 0; c < 8; c++) dq = fmaf(p[c], p[c], dq);
    float dq2 = dq * dq;
    float dm1 = (dq - 1.f) * (dq - 1.f);
    float M[36];
    {
        int e = 0;
#pragma unroll
        for (int c = 0; c < 8; c++)
#pragma unroll
            for (int c2 = c; c2 < 8; c2++) M[e++] = p[c] * p[c2];
    }

#pragma unroll
    for (int e = 0; e < 36; e++) {
        float v = M[e];
        v += __shfl_xor_sync(0xffffffffu, v, 16);
        v += __shfl_xor_sync(0xffffffffu, v, 8);
        v += __shfl_xor_sync(0xffffffffu, v, 4);
        v += __shfl_xor_sync(0xffffffffu, v, 2);
        v += __shfl_xor_sync(0xffffffffu, v, 1);
        if ((tid & 31) == 0) atomicAdd(&g_M[s][b][h][e], v);
    }
    float v2[2] = { dq2, dm1 };
    float* d2[2] = { &g_dq2[s][b][h], &g_dm1[s][b][h] };
#pragma unroll
    for (int e = 0; e < 2; e++) {
        float v = v2[e];
        v += __shfl_xor_sync(0xffffffffu, v, 16);
        v += __shfl_xor_sync(0xffffffffu, v, 8);
        v += __shfl_xor_sync(0xffffffffu, v, 4);
        v += __shfl_xor_sync(0xffffffffu, v, 2);
        v += __shfl_xor_sync(0xffffffffu, v, 1);
        if ((tid & 31) == 0) atomicAdd(d2[e], v);
    }
}

// ---------------- cp.async 6-stage tf32 GEMM, ldmatrix A-feed (rna cvt) ------
#define GSTR 20
#define GSTAGE 18432
#define GNST 6
struct GArgs {
    const float* A[3];
    const float* Bi[3];
    float sc[3];
    int md[3];
    int ws[3];
    float* outp;
};

__global__ __launch_bounds__(256, 2) void gemm_tf32(GArgs ga)
{
    extern __shared__ uint8_t sm[];
    int z = blockIdx.z;
    const float* Ap = ga.A[z];
    if (!Ap) Ap = &g_ctx[0][0][0];
    const float* bias = ga.Bi[z];
    float scale = ga.sc[z];
    int out_mode = ga.md[z];
    int wsel = ga.ws[z];

    int tid = threadIdx.x;
    int lane = tid & 31, wid = tid >> 5;
    int g = lane >> 2, q = lane & 3;
    int wm = wid & 3, wn = wid >> 2;
    int m0 = blockIdx.y * 128, n0 = blockIdx.x * 128;
    int n8base = n0 >> 3;

    int lt = lane >> 3, lr = lane & 7;
    int ldrow = ((lt & 1) << 3) + lr;
    int ldcol = (lt & 2) << 1;

    auto issue = [&](int kc) {
        int stg = kc % GNST;
        uint32_t base = (uint32_t)__cvta_generic_to_shared(sm + stg * GSTAGE);
#pragma unroll
        for (int i = 0; i < 2; i++) {
            int cid = tid + 256 * i;
            int row = cid >> 2, c = cid & 3;
            cp16(base + (row * GSTR + c * 4) * 4,
                 Ap + (size_t)(m0 + row) * 512 + kc * 16 + c * 4);
            int n8b = cid >> 5, ln = cid & 31;
            cp16(base + 10240 + cid * 16, &g_wf[wsel][n8base + n8b][kc][ln]);
        }
        cp_commit();
    };

    float acc[2][8][4];
#pragma unroll
    for (int mt = 0; mt < 2; mt++)
#pragma unroll
        for (int nt = 0; nt < 8; nt++)
#pragma unroll
            for (int s = 0; s < 4; s++) acc[mt][nt][s] = 0.f;

    issue(0); issue(1); issue(2);

    for (int it = 0; it < 16; it++) {
        if (it == 15) cp_wait<0>(); else cp_wait<1>();
        __syncthreads();
        int c3 = 2 * it + 3, c4 = 2 * it + 4;
        if (c3 < 32) issue(c3);
        if (c4 < 32) issue(c4);

        for (int half = 0; half < 2; half++) {
            int kc = 2 * it + half;
            uint32_t As_s = (uint32_t)__cvta_generic_to_shared(sm + (kc % GNST) * GSTAGE);
            const uint4* Bsm = (const uint4*)(sm + (kc % GNST) * GSTAGE + 10240);

            uint4 bfr[8];
#pragma unroll
            for (int nt = 0; nt < 8; nt++)
                bfr[nt] = Bsm[(wn * 8 + nt) * 32 + lane];

#pragma unroll
            for (int ks = 0; ks < 2; ks++) {
                uint32_t a[2][4];
#pragma unroll
                for (int mt = 0; mt < 2; mt++) {
                    int mr = wm * 32 + mt * 16;
                    uint32_t raw[4];
                    ldm4(raw, As_s + ((mr + ldrow) * GSTR + ks * 8 + ldcol) * 4);
                    a[mt][0] = f2tf(__uint_as_float(raw[0]));
                    a[mt][1] = f2tf(__uint_as_float(raw[1]));
                    a[mt][2] = f2tf(__uint_as_float(raw[2]));
                    a[mt][3] = f2tf(__uint_as_float(raw[3]));
                }
#pragma unroll
                for (int nt = 0; nt < 8; nt++) {
                    uint32_t b0 = ks ? bfr[nt].z : bfr[nt].x;
                    uint32_t b1 = ks ? bfr[nt].w : bfr[nt].y;
                    mma8(acc[0][nt], a[0], b0, b1);
                    mma8(acc[1][nt], a[1], b0, b1);
                }
            }
        }
    }

    // ---------- staged epilogue: smem transpose -> coalesced STG.128 -------
    __syncthreads();
    float* S = (float*)sm + wid * 1088;
    int C0 = n0 + wn * 64;
    int hh = C0 >> 6;

#pragma unroll
    for (int mt = 0; mt < 2; mt++) {
        if (mt) __syncwarp();
#pragma unroll
        for (int nt = 0; nt < 8; nt++)
#pragma unroll
            for (int s = 0; s < 4; s++) {
                int r = g + ((s >= 2) ? 8 : 0);
                int ct = nt * 8 + 2 * q + (s & 1);
                S[r * 68 + ct] = (acc[mt][nt][s] + bias[C0 + ct]) * scale;
            }
        __syncwarp();

        int R0 = m0 + wm * 32 + mt * 16;
        if (out_mode == 3) {
#pragma unroll
            for (int it = 0; it < 8; it++) {
                int linear = it * 32 + lane;
                int row = linear >> 4, f4 = linear & 15;
                float4 v = *(const float4*)&S[row * 68 + f4 * 4];
                *(float4*)&ga.outp[(size_t)(R0 + row) * 512 + C0 + f4 * 4] = v;
            }
        } else {
            int bb = R0 >> 10;
            int l0 = R0 & 1023;
            if (out_mode == 0) {
                int l16 = l0 >> 4;
#pragma unroll
                for (int ks = 0; ks < 8; ks++) {
                    uint4 v;
                    v.x = f2tf(S[g * 68 + ks * 8 + q]);
                    v.y = f2tf(S[(g + 8) * 68 + ks * 8 + q]);
                    v.z = f2tf(S[g * 68 + ks * 8 + q + 4]);
                    v.w = f2tf(S[(g + 8) * 68 + ks * 8 + q + 4]);
                    g_qf[bb][hh][l16][ks][lane] = v;
                }
            } else if (out_mode == 1) {
#pragma unroll
                for (int j = 0; j < 2; j++)
#pragma unroll
                    for (int k16 = 0; k16 < 4; k16++) {
                        int rr = j * 8 + g;
                        uint4 v;
                        v.x = f2tf(S[rr * 68 + k16 * 16 + q]);
                        v.y = f2tf(S[rr * 68 + k16 * 16 + q + 4]);
                        v.z = f2tf(S[rr * 68 + k16 * 16 + q + 8]);
                        v.w = f2tf(S[rr * 68 + k16 * 16 + q + 12]);
                        g_kf[bb][hh][(l0 >> 3) + j][k16][lane] = v;
                    }
            } else {
                int k16v = l0 >> 4;
#pragma unroll
                for (int d8 = 0; d8 < 8; d8++) {
                    uint4 v;
                    v.x = f2tf(S[q * 68 + d8 * 8 + g]);
                    v.y = f2tf(S[(q + 4) * 68 + d8 * 8 + g]);
                    v.z = f2tf(S[(q + 8) * 68 + d8 * 8 + g]);
                    v.w = f2tf(S[(q + 12) * 68 + d8 * 8 + g]);
                    g_vf[bb][hh][k16v][d8][lane] = v;
                }
            }
        }
    }
}

// ---------------- fused flash attention: 256 thr, 128 q-rows, 4-stage --------
#define ASTG 37120

__global__ __launch_bounds__(256) void attn_tf32(const float* __restrict__ pm)
{
    extern __shared__ uint8_t sm[];

    int bh = blockIdx.x;
    int b = bh >> 3, h = bh & 7;
    int tid = threadIdx.x;
    int lane = tid & 31, w = tid >> 5;
    int g = lane >> 2, q = lane & 3;
    int q0 = blockIdx.y * 128;
    int r0 = q0 + w * 16 + g;
    int r1 = r0 + 8;

    auto issue = [&](int t, int stg) {
        uint32_t base = (uint32_t)__cvta_generic_to_shared(sm + stg * ASTG);
        const uint4* kg_ = &g_kf[b][h][t * 8][0][0];
        const uint4* vg_ = &g_vf[b][h][t * 4][0][0];
#pragma unroll
        for (int i = 0; i < 4; i++) {
            int cid = tid + 256 * i;
            cp16(base + cid * 16, kg_ + cid);
            cp16(base + 16384 + cid * 16, vg_ + cid);
        }
        cp16(base + 32768 + tid * 16, &g_pkf[b][h][t * 8][0] + tid);
        if (tid < 16)
            cp16(base + 36864 + tid * 16, pm + (size_t)b * LL + t * 64 + tid * 4);
        cp_commit();
    };

    uint32_t qa[8][4];
    {
        int l16 = blockIdx.y * 8 + w;
#pragma unroll
        for (int ks = 0; ks < 8; ks++) {
            uint4 t0 = g_qf[b][h][l16][ks][lane];
            qa[ks][0] = t0.x; qa[ks][1] = t0.y; qa[ks][2] = t0.z; qa[ks][3] = t0.w;
        }
    }
    // Pq A-fragments, exact hi/lo tf32 split (constant across tiles)
    uint32_t ahi[4], alo[4];
    {
        float p00 = g_probs[0][b][h][r0][q];
        float p10 = g_probs[0][b][h][r1][q];
        float p04 = g_probs[0][b][h][r0][q + 4];
        float p14 = g_probs[0][b][h][r1][q + 4];
        ahi[0] = f2tf(p00); alo[0] = f2tf(p00 - __uint_as_float(ahi[0]));
        ahi[1] = f2tf(p10); alo[1] = f2tf(p10 - __uint_as_float(ahi[1]));
        ahi[2] = f2tf(p04); alo[2] = f2tf(p04 - __uint_as_float(ahi[2]));
        ahi[3] = f2tf(p14); alo[3] = f2tf(p14 - __uint_as_float(ahi[3]));
    }

    float accO[8][4];
#pragma unroll
    for (int nt = 0; nt < 8; nt++)
#pragma unroll
        for (int s = 0; s < 4; s++) accO[nt][s] = 0.f;
    float mrow0 = -1e30f, mrow1 = -1e30f, Z0 = 0.f, Z1 = 0.f;

    issue(0, 0);
    issue(1, 1);
    issue(2, 2);

    for (int t = 0; t < 16; t++) {
        if (t >= 14) cp_wait<0>(); else cp_wait<2>();
        __syncthreads();
        if (t + 3 < 16) issue(t + 3, (t + 3) & 3);

        int stg = t & 3;
        const uint4* Ksm = (const uint4*)(sm + stg * ASTG);
        const uint4* Vsm = (const uint4*)(sm + stg * ASTG + 16384);
        const uint4* Pkf = (const uint4*)(sm + stg * ASTG + 32768);
        const float* padk = (const float*)(sm + stg * ASTG + 36864);

        // sim = Pq·Pk^T on the tensor pipe, exact 4-term hi/lo split
        float accS[8][4];
#pragma unroll
        for (int nt = 0; nt < 8; nt++)
#pragma unroll
            for (int s = 0; s < 4; s++) accS[nt][s] = 0.f;
#pragma unroll
        for (int nt = 0; nt < 8; nt++) {
            uint4 pk = Pkf[nt * 32 + lane];
            mma8(accS[nt], ahi, pk.x, pk.y);
            mma8(accS[nt], alo, pk.x, pk.y);
            mma8(accS[nt], ahi, pk.z, pk.w);
            mma8(accS[nt], alo, pk.z, pk.w);
        }

        // sim -> bias = -10000*cmask ; u = 1-cm packed to half2
        __half2 uh0[8], uh1[8];
#pragma unroll
        for (int nt = 0; nt < 8; nt++) {
            float2 pd = *(const float2*)&padk[nt * 8 + 2 * q];
            float cm0 = fminf(fmaxf(1.f - accS[nt][0] + pd.x, 0.f), 1.f);
            float cm1 = fminf(fmaxf(1.f - accS[nt][1] + pd.y, 0.f), 1.f);
            float cm2 = fminf(fmaxf(1.f - accS[nt][2] + pd.x, 0.f), 1.f);
            float cm3 = fminf(fmaxf(1.f - accS[nt][3] + pd.y, 0.f), 1.f);
            accS[nt][0] = -10000.f * cm0;
            accS[nt][1] = -10000.f * cm1;
            accS[nt][2] = -10000.f * cm2;
            accS[nt][3] = -10000.f * cm3;
            uh0[nt] = __floats2half2_rn(1.f - cm0, 1.f - cm1);
            uh1[nt] = __floats2half2_rn(1.f - cm2, 1.f - cm3);
        }

        // S += Q * K^T
#pragma unroll
        for (int ks2 = 0; ks2 < 4; ks2++) {
#pragma unroll
            for (int nt = 0; nt < 8; nt++) {
                uint4 kb = Ksm[(nt * 4 + ks2) * 32 + lane];
                mma8(accS[nt], qa[2 * ks2], kb.x, kb.y);
                mma8(accS[nt], qa[2 * ks2 + 1], kb.z, kb.w);
            }
        }

        // online softmax
        float t0 = accS[0][0], t1v = accS[0][2];
#pragma unroll
        for (int nt = 0; nt < 8; nt++) {
            t0 = fmaxf(t0, fmaxf(accS[nt][0], accS[nt][1]));
            t1v = fmaxf(t1v, fmaxf(accS[nt][2], accS[nt][3]));
        }
        t0 = fmaxf(t0, __shfl_xor_sync(0xffffffffu, t0, 1));
        t0 = fmaxf(t0, __shfl_xor_sync(0xffffffffu, t0, 2));
        t1v = fmaxf(t1v, __shfl_xor_sync(0xffffffffu, t1v, 1));
        t1v = fmaxf(t1v, __shfl_xor_sync(0xffffffffu, t1v, 2));
        float mn0 = fmaxf(mrow0, t0), mn1 = fmaxf(mrow1, t1v);
        float corr0 = __expf(mrow0 - mn0), corr1 = __expf(mrow1 - mn1);
        mrow0 = mn0; mrow1 = mn1;
        Z0 *= corr0; Z1 *= corr1;
#pragma unroll
        for (int nt = 0; nt < 8; nt++) {
            accO[nt][0] *= corr0; accO[nt][1] *= corr0;
            accO[nt][2] *= corr1; accO[nt][3] *= corr1;
        }
        float z0 = 0.f, z1 = 0.f;
#pragma unroll
        for (int nt = 0; nt < 8; nt++) {
            float e0 = __expf(accS[nt][0] - mn0);
            float e1 = __expf(accS[nt][1] - mn0);
            float e2 = __expf(accS[nt][2] - mn1);
            float e3 = __expf(accS[nt][3] - mn1);
            z0 += e0 + e1; z1 += e2 + e3;
            float2 u0 = __half22float2(uh0[nt]);
            float2 u1 = __half22float2(uh1[nt]);
            accS[nt][0] = e0 * u0.x;
            accS[nt][1] = e1 * u0.y;
            accS[nt][2] = e2 * u1.x;
            accS[nt][3] = e3 * u1.y;
        }
        Z0 += z0; Z1 += z1;

        // O += P * V : permute C-frag -> A-frag via quad shuffles
        int srcA = (lane & ~3) | (q >> 1);
        int srcB = srcA + 2;
        bool odd = (q & 1);
#pragma unroll
        for (int kg2 = 0; kg2 < 4; kg2++) {
            uint32_t aP[2][4];
#pragma unroll
            for (int half = 0; half < 2; half++) {
                int kg = 2 * kg2 + half;
                float x0 = __shfl_sync(0xffffffffu, accS[kg][0], srcA);
                float x1 = __shfl_sync(0xffffffffu, accS[kg][1], srcA);
                float x4 = __shfl_sync(0xffffffffu, accS[kg][0], srcB);
                float x5 = __shfl_sync(0xffffffffu, accS[kg][1], srcB);
                float y0 = __shfl_sync(0xffffffffu, accS[kg][2], srcA);
                float y1 = __shfl_sync(0xffffffffu, accS[kg][3], srcA);
                float y4 = __shfl_sync(0xffffffffu, accS[kg][2], srcB);
                float y5 = __shfl_sync(0xffffffffu, accS[kg][3], srcB);
                aP[half][0] = f2tf(odd ? x1 : x0);
                aP[half][1] = f2tf(odd ? y1 : y0);
                aP[half][2] = f2tf(odd ? x5 : x4);
                aP[half][3] = f2tf(odd ? y5 : y4);
            }
#pragma unroll
            for (int nt = 0; nt < 8; nt++) {
                uint4 vb = Vsm[(kg2 * 8 + nt) * 32 + lane];
                mma8(accO[nt], aP[0], vb.x, vb.y);
                mma8(accO[nt], aP[1], vb.z, vb.w);
            }
        }
    }

    Z0 += __shfl_xor_sync(0xffffffffu, Z0, 1);
    Z0 += __shfl_xor_sync(0xffffffffu, Z0, 2);
    Z1 += __shfl_xor_sync(0xffffffffu, Z1, 1);
    Z1 += __shfl_xor_sync(0xffffffffu, Z1, 2);
    float iz0 = 1.f / Z0, iz1 = 1.f / Z1;
#pragma unroll
    for (int nt = 0; nt < 8; nt++) {
        float2 o0 = make_float2(accO[nt][0] * iz0, accO[nt][1] * iz0);
        float2 o1 = make_float2(accO[nt][2] * iz1, accO[nt][3] * iz1);
        *(float2*)&g_ctx[b][r0][h * DK + nt * 8 + 2 * q] = o0;
        *(float2*)&g_ctx[b][r1][h * DK + nt * 8 + 2 * q] = o1;
    }
}

// ---------------- finalize ---------------------------------------------------
__global__ void finalize_kernel(float* __restrict__ out, int out_size)
{
    int b = threadIdx.x;
    if (b >= BB) return;
    float kl = 0.f;
    for (int s = 0; s < 2; s++)
        for (int h = 0; h < HH; h++) kl += g_klsum[s][b][h];
    const float c3 = -0.5f * (1.0f + LOG_AV) * (float)DK;
    float kl_total = kl / (float)(HH * LL) + 2.f * c3;

    float dv = 0.f;
    for (int s = 0; s < 2; s++)
        for (int h = 0; h < HH; h++) {
            float frob = 0.f;
            int e = 0;
            for (int c = 0; c < NC; c++)
                for (int c2 = c; c2 < NC; c2++) {
                    float mv = g_M[s][b][h][e++];
                    frob += (c2 == c) ? mv * mv : 2.f * mv * mv;
                }
            dv += 0.75f * (frob - g_dq2[s][b][h]) + 1.25f * g_dm1[s][b][h];
        }
    dv /= (float)HH * (float)LL * (float)LL;

    long base = (long)BB * LL * DMODEL;
    if (out_size >= base + 2 * BB) {
        out[base + b] = kl_total;
        out[base + BB + b] = dv;
    }
}

// ---------------- launch -----------------------------------------------------
extern "C" void kernel_launch(void* const* d_in, const int* in_sizes, int n_in,
                              void* d_out, int out_size)
{
    const float* query  = (const float*)d_in[0];
    const float* key    = (const float*)d_in[1];
    const float* value  = (const float*)d_in[2];
    const float* pmask  = (const float*)d_in[3];
    const float* Wq = (const float*)d_in[4];
    const float* bq = (const float*)d_in[5];
    const float* Wk = (const float*)d_in[6];
    const float* bk = (const float*)d_in[7];
    const float* Wv = (const float*)d_in[8];
    const float* bv = (const float*)d_in[9];
    const float* Wo = (const float*)d_in[10];
    const float* bo = (const float*)d_in[11];
    const float* tok_mu = (const float*)d_in[12];
    const float* tok_lv = (const float*)d_in[13];
    const float* tok_lp = (const float*)d_in[14];
    float* outp = (float*)d_out;

    cudaFuncSetAttribute(gemm_tf32, cudaFuncAttributeMaxDynamicSharedMemorySize, GNST * GSTAGE);
    cudaFuncSetAttribute(attn_tf32, cudaFuncAttributeMaxDynamicSharedMemorySize, 4 * ASTG);

    cudaStream_t sB;
    cudaStreamCreateWithFlags(&sB, cudaStreamNonBlocking);
    cudaEvent_t evFork, evProbs, evStats;
    cudaEventCreateWithFlags(&evFork, cudaEventDisableTiming);
    cudaEventCreateWithFlags(&evProbs, cudaEventDisableTiming);
    cudaEventCreateWithFlags(&evStats, cudaEventDisableTiming);

    cudaEventRecord(evFork, 0);
    cudaStreamWaitEvent(sB, evFork, 0);

    // branch B: zero -> clustering -> pack_pk -> (evProbs) -> stats -> (evStats)
    zero_kernel<<<1, 256, 0, sB>>>();
    clustering_kernel<<<dim3(2 * BB * HH, 4), 256, 0, sB>>>(query, key, tok_mu, tok_lv, tok_lp);
    pack_pk<<<512, 256, 0, sB>>>();
    cudaEventRecord(evProbs, sB);
    stats_kernel<<<256, 256, 0, sB>>>();
    cudaEventRecord(evStats, sB);

    // branch A: pack_w -> QKV gemm
    PArgs pw;
    pw.W[0] = Wq; pw.W[1] = Wk; pw.W[2] = Wv; pw.W[3] = Wo;
    pack_w<<<256, 256>>>(pw);

    GArgs qkv;
    qkv.A[0] = query; qkv.A[1] = key; qkv.A[2] = value;
    qkv.Bi[0] = bq;   qkv.Bi[1] = bk; qkv.Bi[2] = bv;
    qkv.sc[0] = 0.125f; qkv.sc[1] = 1.f; qkv.sc[2] = 1.f;
    qkv.md[0] = 0; qkv.md[1] = 1; qkv.md[2] = 2;
    qkv.ws[0] = 0; qkv.ws[1] = 1; qkv.ws[2] = 2;
    qkv.outp = nullptr;
    gemm_tf32<<<dim3(4, 32, 3), 256, GNST * GSTAGE>>>(qkv);

    cudaStreamWaitEvent(0, evProbs, 0);
    attn_tf32<<<dim3(BB * HH, LL / 128), 256, 4 * ASTG>>>(pmask);

    GArgs og;
    og.A[0] = nullptr; og.A[1] = nullptr; og.A[2] = nullptr;
    og.Bi[0] = bo; og.Bi[1] = bo; og.Bi[2] = bo;
    og.sc[0] = 1.f; og.sc[1] = 1.f; og.sc[2] = 1.f;
    og.md[0] = 3; og.md[1] = 3; og.md[2] = 3;
    og.ws[0] = 3; og.ws[1] = 3; og.ws[2] = 3;
    og.outp = outp;
    gemm_tf32<<<dim3(4, 32, 1), 256, GNST * GSTAGE>>>(og);

    cudaStreamWaitEvent(0, evStats, 0);
    finalize_kernel<<<1, 32>>>(outp, out_size);
}

// round 16
// speedup vs baseline: 1.0785x; 1.0180x over previous
#include <cuda_runtime.h>
#include <math.h>
#include <stdint.h>

#define BB 4
#define LL 1024
#define DMODEL 512
#define HH 8
#define NC 8
#define DK 64
#define LOG_AV (-4.605170185988091f)   // log(0.01)

// ---------------- scratch (device globals: no allocation allowed) ----------
__device__ __align__(256) float g_probs[2][BB][HH][LL][NC]; // 0=q,1=k
__device__ __align__(256) uint4 g_qf[BB][HH][64][8][32];
__device__ __align__(256) uint4 g_kf[BB][HH][128][4][32];
__device__ __align__(256) uint4 g_vf[BB][HH][64][8][32];
__device__ __align__(256) uint4 g_wf[4][64][32][32];
// Pk B-fragments, hi/lo tf32 split: [n8 block][lane]{b0hi,b1hi,b0lo,b1lo}
__device__ __align__(256) uint4 g_pkf[BB][HH][128][32];
__device__ __align__(256) float g_ctx[BB][LL][DMODEL];
__device__ float g_M[2][BB][HH][36];
__device__ float g_klsum[2][BB][HH];
__device__ float g_dq2[2][BB][HH];
__device__ float g_dm1[2][BB][HH];

// ---------------- helpers ---------------------------------------------------
__device__ __forceinline__ uint32_t f2tf(float x) {
    uint32_t r;
    asm("cvt.rna.tf32.f32 %0, %1;" : "=r"(r) : "f"(x));
    return r;
}
__device__ __forceinline__ void mma8(float* c, const uint32_t* a, uint32_t b0, uint32_t b1) {
    asm volatile(
        "mma.sync.aligned.m16n8k8.row.col.f32.tf32.tf32.f32 "
        "{%0,%1,%2,%3}, {%4,%5,%6,%7}, {%8,%9}, {%0,%1,%2,%3};"
        : "+f"(c[0]), "+f"(c[1]), "+f"(c[2]), "+f"(c[3])
        : "r"(a[0]), "r"(a[1]), "r"(a[2]), "r"(a[3]), "r"(b0), "r"(b1));
}
__device__ __forceinline__ void ldm4(uint32_t* r, uint32_t saddr) {
    asm volatile("ldmatrix.sync.aligned.m8n8.x4.shared.b16 {%0,%1,%2,%3}, [%4];"
        : "=r"(r[0]), "=r"(r[1]), "=r"(r[2]), "=r"(r[3]) : "r"(saddr));
}
__device__ __forceinline__ void cp16(uint32_t saddr, const void* gptr) {
    asm volatile("cp.async.cg.shared.global [%0], [%1], 16;" :: "r"(saddr), "l"(gptr));
}
__device__ __forceinline__ void cp_commit() { asm volatile("cp.async.commit_group;"); }
template<int N> __device__ __forceinline__ void cp_wait() {
    asm volatile("cp.async.wait_group %0;" :: "n"(N));
}

// ---------------- zero accumulators ----------------------------------------
__global__ void zero_kernel() {
    int i = threadIdx.x;
    float* pM = &g_M[0][0][0][0];
    for (int e = i; e < 2 * BB * HH * 36; e += 256) pM[e] = 0.f;
    float* pk = &g_klsum[0][0][0];
    float* pd = &g_dq2[0][0][0];
    float* pm = &g_dm1[0][0][0];
    for (int e = i; e < 2 * BB * HH; e += 256) { pk[e] = 0.f; pd[e] = 0.f; pm[e] = 0.f; }
}

// ---------------- weight pack v2 --------------------------------------------
struct PArgs { const float* W[4]; };
__global__ __launch_bounds__(256) void pack_w(PArgs pa) {
    int idx = blockIdx.x * 256 + threadIdx.x;   // 65536
    int g = idx & 7;
    int k16 = (idx >> 3) & 31;
    int n8 = (idx >> 8) & 63;
    int w = idx >> 14;
    const float* src = pa.W[w] + (size_t)(n8 * 8 + g) * 512 + k16 * 16;
    float4 v0 = *(const float4*)(src);
    float4 v1 = *(const float4*)(src + 4);
    float4 v2 = *(const float4*)(src + 8);
    float4 v3 = *(const float4*)(src + 12);
    float c0[4] = { v0.x, v0.y, v0.z, v0.w };
    float c1[4] = { v1.x, v1.y, v1.z, v1.w };
    float c2[4] = { v2.x, v2.y, v2.z, v2.w };
    float c3[4] = { v3.x, v3.y, v3.z, v3.w };
#pragma unroll
    for (int q = 0; q < 4; q++) {
        uint4 o;
        o.x = f2tf(c0[q]); o.y = f2tf(c1[q]); o.z = f2tf(c2[q]); o.w = f2tf(c3[q]);
        g_wf[w][n8][k16][g * 4 + q] = o;
    }
}

// ---------------- pack Pk into hi/lo tf32 B-fragments -----------------------
__global__ __launch_bounds__(256) void pack_pk() {
    int idx = blockIdx.x * 256 + threadIdx.x;   // 131072
    int lane = idx & 31;
    int n8 = (idx >> 5) & 127;
    int h = (idx >> 12) & 7;
    int b = idx >> 15;
    int g = lane >> 2, q = lane & 3;
    int key = n8 * 8 + g;
    float v0 = g_probs[1][b][h][key][q];
    float v1 = g_probs[1][b][h][key][q + 4];
    uint32_t h0 = f2tf(v0), h1 = f2tf(v1);
    uint32_t l0 = f2tf(v0 - __uint_as_float(h0));
    uint32_t l1 = f2tf(v1 - __uint_as_float(h1));
    g_pkf[b][h][n8][lane] = make_uint4(h0, h1, l0, l1);
}

// ---------------- clustering: probs + kl only -------------------------------
__global__ __launch_bounds__(256) void clustering_kernel(
    const float* __restrict__ qin, const float* __restrict__ kin,
    const float* __restrict__ mu, const float* __restrict__ logvar,
    const float* __restrict__ logprior)
{
    __shared__ float4 mu4[NC][16];
    __shared__ float4 iv4[NC][16];
    __shared__ float lvs_s[NC], ratio_s[NC], logp_s[NC], prior_s[NC];

    int bx = blockIdx.x;
    int s = bx >> 5;
    int rem = bx & 31;
    int b = rem >> 3;
    int h = rem & 7;
    int tid = threadIdx.x;
    int l = blockIdx.y * 256 + tid;

    if (tid < NC * 16) {
        int c = tid >> 4, d4 = tid & 15;
        const float* msrc = &mu[(h * NC + c) * DK + d4 * 4];
        const float* lsrc = &logvar[(h * NC + c) * DK + d4 * 4];
        float4 mv = make_float4(msrc[0], msrc[1], msrc[2], msrc[3]);
        float4 ivv = make_float4(expf(-lsrc[0]), expf(-lsrc[1]), expf(-lsrc[2]), expf(-lsrc[3]));
        mu4[c][d4] = mv;
        iv4[c][d4] = ivv;
    }
    __syncthreads();
    if (tid < NC) {
        float ls = 0.f, rs = 0.f;
        const float avar = expf(LOG_AV);
        for (int d4 = 0; d4 < 16; d4++) {
            float4 ivv = iv4[tid][d4];
            rs += ivv.x + ivv.y + ivv.z + ivv.w;
        }
        for (int d = 0; d < DK; d++)
            ls += logvar[(h * NC + tid) * DK + d];
        lvs_s[tid] = ls;
        ratio_s[tid] = avar * rs;
    }
    if (tid == 0) {
        float mx = -1e30f;
        for (int c = 0; c < NC; c++) mx = fmaxf(mx, logprior[h * NC + c]);
        float ss = 0.f;
        for (int c = 0; c < NC; c++) ss += expf(logprior[h * NC + c] - mx);
        float lse = mx + logf(ss);
        for (int c = 0; c < NC; c++) {
            logp_s[c] = logprior[h * NC + c] - lse;
            prior_s[c] = expf(logp_s[c]);
        }
    }
    __syncthreads();

    const float* src = (s == 0) ? qin : kin;
    const float4* xr4 = (const float4*)(src + ((size_t)b * LL + l) * DMODEL + h * DK);

    float4 x4[16];
#pragma unroll
    for (int dd = 0; dd < 16; dd++) x4[dd] = xr4[dd];

    float mse[NC], logit[NC];
#pragma unroll
    for (int c = 0; c < NC; c++) {
        float a = 0.f;
#pragma unroll
        for (int d4 = 0; d4 < 16; d4++) {
            float4 mv = mu4[c][d4];
            float4 ivv = iv4[c][d4];
            float t0 = x4[d4].x - mv.x; a = fmaf(t0 * t0, ivv.x, a);
            float t1 = x4[d4].y - mv.y; a = fmaf(t1 * t1, ivv.y, a);
            float t2 = x4[d4].z - mv.z; a = fmaf(t2 * t2, ivv.z, a);
            float t3 = x4[d4].w - mv.w; a = fmaf(t3 * t3, ivv.w, a);
        }
        mse[c] = a;
        logit[c] = -0.5f * a - 0.5f * lvs_s[c] + logp_s[c];
    }
    float m = logit[0];
#pragma unroll
    for (int c = 1; c < NC; c++) m = fmaxf(m, logit[c]);
    float p[NC];
    float Zl = 0.f;
#pragma unroll
    for (int c = 0; c < NC; c++) { p[c] = expf(logit[c] - m); Zl += p[c]; }
    float lz = logf(Zl);
    float inv = 1.f / Zl;

    float t1 = 0.f;
#pragma unroll
    for (int c = 0; c < NC; c++)
        t1 += prior_s[c] * (logp_s[c] - (logit[c] - m - lz));
#pragma unroll
    for (int c = 0; c < NC; c++) p[c] *= inv;
    float t2 = 0.f;
#pragma unroll
    for (int c = 0; c < NC; c++)
        t2 += p[c] * (mse[c] + ratio_s[c] + lvs_s[c]);
    float klloc = t1 + 0.5f * t2;

#pragma unroll
    for (int c = 0; c < NC; c++) g_probs[s][b][h][l][c] = p[c];

    float v = klloc;
    v += __shfl_xor_sync(0xffffffffu, v, 16);
    v += __shfl_xor_sync(0xffffffffu, v, 8);
    v += __shfl_xor_sync(0xffffffffu, v, 4);
    v += __shfl_xor_sync(0xffffffffu, v, 2);
    v += __shfl_xor_sync(0xffffffffu, v, 1);
    if ((tid & 31) == 0) atomicAdd(&g_klsum[s][b][h], v);
}

// ---------------- stats: M = P^T P upper-tri, dq2, dm1 ----------------------
__global__ __launch_bounds__(256) void stats_kernel()
{
    int sbh = blockIdx.x >> 2;
    int chunk = blockIdx.x & 3;
    int s = sbh >> 5, b = (sbh >> 3) & 3, h = sbh & 7;
    int tid = threadIdx.x;
    int l = chunk * 256 + tid;

    float4 pA = *(const float4*)&g_probs[s][b][h][l][0];
    float4 pB = *(const float4*)&g_probs[s][b][h][l][4];
    float p[8] = { pA.x, pA.y, pA.z, pA.w, pB.x, pB.y, pB.z, pB.w };
    float dq = 0.f;
#pragma unroll
    for (int c = 0; c < 8; c++) dq = fmaf(p[c], p[c], dq);
    float dq2 = dq * dq;
    float dm1 = (dq - 1.f) * (dq - 1.f);
    float M[36];
    {
        int e = 0;
#pragma unroll
        for (int c = 0; c < 8; c++)
#pragma unroll
            for (int c2 = c; c2 < 8; c2++) M[e++] = p[c] * p[c2];
    }

#pragma unroll
    for (int e = 0; e < 36; e++) {
        float v = M[e];
        v += __shfl_xor_sync(0xffffffffu, v, 16);
        v += __shfl_xor_sync(0xffffffffu, v, 8);
        v += __shfl_xor_sync(0xffffffffu, v, 4);
        v += __shfl_xor_sync(0xffffffffu, v, 2);
        v += __shfl_xor_sync(0xffffffffu, v, 1);
        if ((tid & 31) == 0) atomicAdd(&g_M[s][b][h][e], v);
    }
    float v2[2] = { dq2, dm1 };
    float* d2[2] = { &g_dq2[s][b][h], &g_dm1[s][b][h] };
#pragma unroll
    for (int e = 0; e < 2; e++) {
        float v = v2[e];
        v += __shfl_xor_sync(0xffffffffu, v, 16);
        v += __shfl_xor_sync(0xffffffffu, v, 8);
        v += __shfl_xor_sync(0xffffffffu, v, 4);
        v += __shfl_xor_sync(0xffffffffu, v, 2);
        v += __shfl_xor_sync(0xffffffffu, v, 1);
        if ((tid & 31) == 0) atomicAdd(d2[e], v);
    }
}

// ---------------- cp.async 6-stage tf32 GEMM, ldmatrix A-feed (rna cvt) ------
#define GSTR 20
#define GSTAGE 18432
#define GNST 6
struct GArgs {
    const float* A[3];
    const float* Bi[3];
    float sc[3];
    int md[3];
    int ws[3];
    float* outp;
};

__global__ __launch_bounds__(256, 2) void gemm_tf32(GArgs ga)
{
    extern __shared__ uint8_t sm[];
    int z = blockIdx.z;
    const float* Ap = ga.A[z];
    if (!Ap) Ap = &g_ctx[0][0][0];
    const float* bias = ga.Bi[z];
    float scale = ga.sc[z];
    int out_mode = ga.md[z];
    int wsel = ga.ws[z];

    int tid = threadIdx.x;
    int lane = tid & 31, wid = tid >> 5;
    int g = lane >> 2, q = lane & 3;
    int wm = wid & 3, wn = wid >> 2;
    int m0 = blockIdx.y * 128, n0 = blockIdx.x * 128;
    int n8base = n0 >> 3;

    int lt = lane >> 3, lr = lane & 7;
    int ldrow = ((lt & 1) << 3) + lr;
    int ldcol = (lt & 2) << 1;

    auto issue = [&](int kc) {
        int stg = kc % GNST;
        uint32_t base = (uint32_t)__cvta_generic_to_shared(sm + stg * GSTAGE);
#pragma unroll
        for (int i = 0; i < 2; i++) {
            int cid = tid + 256 * i;
            int row = cid >> 2, c = cid & 3;
            cp16(base + (row * GSTR + c * 4) * 4,
                 Ap + (size_t)(m0 + row) * 512 + kc * 16 + c * 4);
            int n8b = cid >> 5, ln = cid & 31;
            cp16(base + 10240 + cid * 16, &g_wf[wsel][n8base + n8b][kc][ln]);
        }
        cp_commit();
    };

    float acc[2][8][4];
#pragma unroll
    for (int mt = 0; mt < 2; mt++)
#pragma unroll
        for (int nt = 0; nt < 8; nt++)
#pragma unroll
            for (int s = 0; s < 4; s++) acc[mt][nt][s] = 0.f;

    issue(0); issue(1); issue(2);

    for (int it = 0; it < 16; it++) {
        if (it == 15) cp_wait<0>(); else cp_wait<1>();
        __syncthreads();
        int c3 = 2 * it + 3, c4 = 2 * it + 4;
        if (c3 < 32) issue(c3);
        if (c4 < 32) issue(c4);

        for (int half = 0; half < 2; half++) {
            int kc = 2 * it + half;
            uint32_t As_s = (uint32_t)__cvta_generic_to_shared(sm + (kc % GNST) * GSTAGE);
            const uint4* Bsm = (const uint4*)(sm + (kc % GNST) * GSTAGE + 10240);

            uint4 bfr[8];
#pragma unroll
            for (int nt = 0; nt < 8; nt++)
                bfr[nt] = Bsm[(wn * 8 + nt) * 32 + lane];

#pragma unroll
            for (int ks = 0; ks < 2; ks++) {
                uint32_t a[2][4];
#pragma unroll
                for (int mt = 0; mt < 2; mt++) {
                    int mr = wm * 32 + mt * 16;
                    uint32_t raw[4];
                    ldm4(raw, As_s + ((mr + ldrow) * GSTR + ks * 8 + ldcol) * 4);
                    a[mt][0] = f2tf(__uint_as_float(raw[0]));
                    a[mt][1] = f2tf(__uint_as_float(raw[1]));
                    a[mt][2] = f2tf(__uint_as_float(raw[2]));
                    a[mt][3] = f2tf(__uint_as_float(raw[3]));
                }
#pragma unroll
                for (int nt = 0; nt < 8; nt++) {
                    uint32_t b0 = ks ? bfr[nt].z : bfr[nt].x;
                    uint32_t b1 = ks ? bfr[nt].w : bfr[nt].y;
                    mma8(acc[0][nt], a[0], b0, b1);
                    mma8(acc[1][nt], a[1], b0, b1);
                }
            }
        }
    }

    // ---------- staged epilogue: smem transpose -> coalesced STG.128 -------
    __syncthreads();
    float* S = (float*)sm + wid * 1088;
    int C0 = n0 + wn * 64;
    int hh = C0 >> 6;

#pragma unroll
    for (int mt = 0; mt < 2; mt++) {
        if (mt) __syncwarp();
#pragma unroll
        for (int nt = 0; nt < 8; nt++)
#pragma unroll
            for (int s = 0; s < 4; s++) {
                int r = g + ((s >= 2) ? 8 : 0);
                int ct = nt * 8 + 2 * q + (s & 1);
                S[r * 68 + ct] = (acc[mt][nt][s] + bias[C0 + ct]) * scale;
            }
        __syncwarp();

        int R0 = m0 + wm * 32 + mt * 16;
        if (out_mode == 3) {
#pragma unroll
            for (int it = 0; it < 8; it++) {
                int linear = it * 32 + lane;
                int row = linear >> 4, f4 = linear & 15;
                float4 v = *(const float4*)&S[row * 68 + f4 * 4];
                *(float4*)&ga.outp[(size_t)(R0 + row) * 512 + C0 + f4 * 4] = v;
            }
        } else {
            int bb = R0 >> 10;
            int l0 = R0 & 1023;
            if (out_mode == 0) {
                int l16 = l0 >> 4;
#pragma unroll
                for (int ks = 0; ks < 8; ks++) {
                    uint4 v;
                    v.x = f2tf(S[g * 68 + ks * 8 + q]);
                    v.y = f2tf(S[(g + 8) * 68 + ks * 8 + q]);
                    v.z = f2tf(S[g * 68 + ks * 8 + q + 4]);
                    v.w = f2tf(S[(g + 8) * 68 + ks * 8 + q + 4]);
                    g_qf[bb][hh][l16][ks][lane] = v;
                }
            } else if (out_mode == 1) {
#pragma unroll
                for (int j = 0; j < 2; j++)
#pragma unroll
                    for (int k16 = 0; k16 < 4; k16++) {
                        int rr = j * 8 + g;
                        uint4 v;
                        v.x = f2tf(S[rr * 68 + k16 * 16 + q]);
                        v.y = f2tf(S[rr * 68 + k16 * 16 + q + 4]);
                        v.z = f2tf(S[rr * 68 + k16 * 16 + q + 8]);
                        v.w = f2tf(S[rr * 68 + k16 * 16 + q + 12]);
                        g_kf[bb][hh][(l0 >> 3) + j][k16][lane] = v;
                    }
            } else {
                int k16v = l0 >> 4;
#pragma unroll
                for (int d8 = 0; d8 < 8; d8++) {
                    uint4 v;
                    v.x = f2tf(S[q * 68 + d8 * 8 + g]);
                    v.y = f2tf(S[(q + 4) * 68 + d8 * 8 + g]);
                    v.z = f2tf(S[(q + 8) * 68 + d8 * 8 + g]);
                    v.w = f2tf(S[(q + 12) * 68 + d8 * 8 + g]);
                    g_vf[bb][hh][k16v][d8][lane] = v;
                }
            }
        }
    }
}

// ---------------- fused flash attention: 256 thr, 128 q-rows, 3-stage --------
#define ASTG 37120

__global__ __launch_bounds__(256) void attn_tf32(const float* __restrict__ pm)
{
    extern __shared__ uint8_t sm[];

    int bh = blockIdx.x;
    int b = bh >> 3, h = bh & 7;
    int tid = threadIdx.x;
    int lane = tid & 31, w = tid >> 5;
    int g = lane >> 2, q = lane & 3;
    int q0 = blockIdx.y * 128;
    int r0 = q0 + w * 16 + g;
    int r1 = r0 + 8;

    auto issue = [&](int t, int stg) {
        uint32_t base = (uint32_t)__cvta_generic_to_shared(sm + stg * ASTG);
        const uint4* kg_ = &g_kf[b][h][t * 8][0][0];
        const uint4* vg_ = &g_vf[b][h][t * 4][0][0];
#pragma unroll
        for (int i = 0; i < 4; i++) {
            int cid = tid + 256 * i;
            cp16(base + cid * 16, kg_ + cid);
            cp16(base + 16384 + cid * 16, vg_ + cid);
        }
        cp16(base + 32768 + tid * 16, &g_pkf[b][h][t * 8][0] + tid);
        if (tid < 16)
            cp16(base + 36864 + tid * 16, pm + (size_t)b * LL + t * 64 + tid * 4);
        cp_commit();
    };

    uint32_t qa[8][4];
    {
        int l16 = blockIdx.y * 8 + w;
#pragma unroll
        for (int ks = 0; ks < 8; ks++) {
            uint4 t0 = g_qf[b][h][l16][ks][lane];
            qa[ks][0] = t0.x; qa[ks][1] = t0.y; qa[ks][2] = t0.z; qa[ks][3] = t0.w;
        }
    }
    // Pq A-fragments, exact hi/lo tf32 split (constant across tiles)
    uint32_t ahi[4], alo[4];
    {
        float p00 = g_probs[0][b][h][r0][q];
        float p10 = g_probs[0][b][h][r1][q];
        float p04 = g_probs[0][b][h][r0][q + 4];
        float p14 = g_probs[0][b][h][r1][q + 4];
        ahi[0] = f2tf(p00); alo[0] = f2tf(p00 - __uint_as_float(ahi[0]));
        ahi[1] = f2tf(p10); alo[1] = f2tf(p10 - __uint_as_float(ahi[1]));
        ahi[2] = f2tf(p04); alo[2] = f2tf(p04 - __uint_as_float(ahi[2]));
        ahi[3] = f2tf(p14); alo[3] = f2tf(p14 - __uint_as_float(ahi[3]));
    }

    float accO[8][4];
#pragma unroll
    for (int nt = 0; nt < 8; nt++)
#pragma unroll
        for (int s = 0; s < 4; s++) accO[nt][s] = 0.f;
    float mrow0 = -1e30f, mrow1 = -1e30f, Z0 = 0.f, Z1 = 0.f;

    issue(0, 0);
    issue(1, 1);

    for (int t = 0; t < 16; t++) {
        if (t == 15) cp_wait<0>(); else cp_wait<1>();
        __syncthreads();
        if (t + 2 < 16) issue(t + 2, (t + 2) % 3);

        int stg = t % 3;
        const uint4* Ksm = (const uint4*)(sm + stg * ASTG);
        const uint4* Vsm = (const uint4*)(sm + stg * ASTG + 16384);
        const uint4* Pkf = (const uint4*)(sm + stg * ASTG + 32768);
        const float* padk = (const float*)(sm + stg * ASTG + 36864);

        // sim = Pq·Pk^T on the tensor pipe, exact 4-term hi/lo split
        float accS[8][4];
#pragma unroll
        for (int nt = 0; nt < 8; nt++)
#pragma unroll
            for (int s = 0; s < 4; s++) accS[nt][s] = 0.f;
#pragma unroll
        for (int nt = 0; nt < 8; nt++) {
            uint4 pk = Pkf[nt * 32 + lane];
            mma8(accS[nt], ahi, pk.x, pk.y);
            mma8(accS[nt], alo, pk.x, pk.y);
            mma8(accS[nt], ahi, pk.z, pk.w);
            mma8(accS[nt], alo, pk.z, pk.w);
        }

        // sim -> bias = -10000*cmask ; u = 1-cm kept in fp32 (regs are free:
        // occupancy is smem-bound at 1 CTA/SM, so no half2 round-trip)
        float u[8][4];
#pragma unroll
        for (int nt = 0; nt < 8; nt++) {
            float2 pd = *(const float2*)&padk[nt * 8 + 2 * q];
            float cm0 = fminf(fmaxf(1.f - accS[nt][0] + pd.x, 0.f), 1.f);
            float cm1 = fminf(fmaxf(1.f - accS[nt][1] + pd.y, 0.f), 1.f);
            float cm2 = fminf(fmaxf(1.f - accS[nt][2] + pd.x, 0.f), 1.f);
            float cm3 = fminf(fmaxf(1.f - accS[nt][3] + pd.y, 0.f), 1.f);
            accS[nt][0] = -10000.f * cm0;
            accS[nt][1] = -10000.f * cm1;
            accS[nt][2] = -10000.f * cm2;
            accS[nt][3] = -10000.f * cm3;
            u[nt][0] = 1.f - cm0;
            u[nt][1] = 1.f - cm1;
            u[nt][2] = 1.f - cm2;
            u[nt][3] = 1.f - cm3;
        }

        // S += Q * K^T
#pragma unroll
        for (int ks2 = 0; ks2 < 4; ks2++) {
#pragma unroll
            for (int nt = 0; nt < 8; nt++) {
                uint4 kb = Ksm[(nt * 4 + ks2) * 32 + lane];
                mma8(accS[nt], qa[2 * ks2], kb.x, kb.y);
                mma8(accS[nt], qa[2 * ks2 + 1], kb.z, kb.w);
            }
        }

        // online softmax
        float t0 = accS[0][0], t1v = accS[0][2];
#pragma unroll
        for (int nt = 0; nt < 8; nt++) {
            t0 = fmaxf(t0, fmaxf(accS[nt][0], accS[nt][1]));
            t1v = fmaxf(t1v, fmaxf(accS[nt][2], accS[nt][3]));
        }
        t0 = fmaxf(t0, __shfl_xor_sync(0xffffffffu, t0, 1));
        t0 = fmaxf(t0, __shfl_xor_sync(0xffffffffu, t0, 2));
        t1v = fmaxf(t1v, __shfl_xor_sync(0xffffffffu, t1v, 1));
        t1v = fmaxf(t1v, __shfl_xor_sync(0xffffffffu, t1v, 2));
        float mn0 = fmaxf(mrow0, t0), mn1 = fmaxf(mrow1, t1v);
        float corr0 = __expf(mrow0 - mn0), corr1 = __expf(mrow1 - mn1);
        mrow0 = mn0; mrow1 = mn1;
        Z0 *= corr0; Z1 *= corr1;
#pragma unroll
        for (int nt = 0; nt < 8; nt++) {
            accO[nt][0] *= corr0; accO[nt][1] *= corr0;
            accO[nt][2] *= corr1; accO[nt][3] *= corr1;
        }
        float z0 = 0.f, z1 = 0.f;
#pragma unroll
        for (int nt = 0; nt < 8; nt++) {
            float e0 = __expf(accS[nt][0] - mn0);
            float e1 = __expf(accS[nt][1] - mn0);
            float e2 = __expf(accS[nt][2] - mn1);
            float e3 = __expf(accS[nt][3] - mn1);
            z0 += e0 + e1; z1 += e2 + e3;
            accS[nt][0] = e0 * u[nt][0];
            accS[nt][1] = e1 * u[nt][1];
            accS[nt][2] = e2 * u[nt][2];
            accS[nt][3] = e3 * u[nt][3];
        }
        Z0 += z0; Z1 += z1;

        // O += P * V : permute C-frag -> A-frag via quad shuffles
        int srcA = (lane & ~3) | (q >> 1);
        int srcB = srcA + 2;
        bool odd = (q & 1);
#pragma unroll
        for (int kg2 = 0; kg2 < 4; kg2++) {
            uint32_t aP[2][4];
#pragma unroll
            for (int half = 0; half < 2; half++) {
                int kg = 2 * kg2 + half;
                float x0 = __shfl_sync(0xffffffffu, accS[kg][0], srcA);
                float x1 = __shfl_sync(0xffffffffu, accS[kg][1], srcA);
                float x4 = __shfl_sync(0xffffffffu, accS[kg][0], srcB);
                float x5 = __shfl_sync(0xffffffffu, accS[kg][1], srcB);
                float y0 = __shfl_sync(0xffffffffu, accS[kg][2], srcA);
                float y1 = __shfl_sync(0xffffffffu, accS[kg][3], srcA);
                float y4 = __shfl_sync(0xffffffffu, accS[kg][2], srcB);
                float y5 = __shfl_sync(0xffffffffu, accS[kg][3], srcB);
                aP[half][0] = f2tf(odd ? x1 : x0);
                aP[half][1] = f2tf(odd ? y1 : y0);
                aP[half][2] = f2tf(odd ? x5 : x4);
                aP[half][3] = f2tf(odd ? y5 : y4);
            }
#pragma unroll
            for (int nt = 0; nt < 8; nt++) {
                uint4 vb = Vsm[(kg2 * 8 + nt) * 32 + lane];
                mma8(accO[nt], aP[0], vb.x, vb.y);
                mma8(accO[nt], aP[1], vb.z, vb.w);
            }
        }
    }

    Z0 += __shfl_xor_sync(0xffffffffu, Z0, 1);
    Z0 += __shfl_xor_sync(0xffffffffu, Z0, 2);
    Z1 += __shfl_xor_sync(0xffffffffu, Z1, 1);
    Z1 += __shfl_xor_sync(0xffffffffu, Z1, 2);
    float iz0 = 1.f / Z0, iz1 = 1.f / Z1;
#pragma unroll
    for (int nt = 0; nt < 8; nt++) {
        float2 o0 = make_float2(accO[nt][0] * iz0, accO[nt][1] * iz0);
        float2 o1 = make_float2(accO[nt][2] * iz1, accO[nt][3] * iz1);
        *(float2*)&g_ctx[b][r0][h * DK + nt * 8 + 2 * q] = o0;
        *(float2*)&g_ctx[b][r1][h * DK + nt * 8 + 2 * q] = o1;
    }
}

// ---------------- finalize ---------------------------------------------------
__global__ void finalize_kernel(float* __restrict__ out, int out_size)
{
    int b = threadIdx.x;
    if (b >= BB) return;
    float kl = 0.f;
    for (int s = 0; s < 2; s++)
        for (int h = 0; h < HH; h++) kl += g_klsum[s][b][h];
    const float c3 = -0.5f * (1.0f + LOG_AV) * (float)DK;
    float kl_total = kl / (float)(HH * LL) + 2.f * c3;

    float dv = 0.f;
    for (int s = 0; s < 2; s++)
        for (int h = 0; h < HH; h++) {
            float frob = 0.f;
            int e = 0;
            for (int c = 0; c < NC; c++)
                for (int c2 = c; c2 < NC; c2++) {
                    float mv = g_M[s][b][h][e++];
                    frob += (c2 == c) ? mv * mv : 2.f * mv * mv;
                }
            dv += 0.75f * (frob - g_dq2[s][b][h]) + 1.25f * g_dm1[s][b][h];
        }
    dv /= (float)HH * (float)LL * (float)LL;

    long base = (long)BB * LL * DMODEL;
    if (out_size >= base + 2 * BB) {
        out[base + b] = kl_total;
        out[base + BB + b] = dv;
    }
}

// ---------------- launch -----------------------------------------------------
extern "C" void kernel_launch(void* const* d_in, const int* in_sizes, int n_in,
                              void* d_out, int out_size)
{
    const float* query  = (const float*)d_in[0];
    const float* key    = (const float*)d_in[1];
    const float* value  = (const float*)d_in[2];
    const float* pmask  = (const float*)d_in[3];
    const float* Wq = (const float*)d_in[4];
    const float* bq = (const float*)d_in[5];
    const float* Wk = (const float*)d_in[6];
    const float* bk = (const float*)d_in[7];
    const float* Wv = (const float*)d_in[8];
    const float* bv = (const float*)d_in[9];
    const float* Wo = (const float*)d_in[10];
    const float* bo = (const float*)d_in[11];
    const float* tok_mu = (const float*)d_in[12];
    const float* tok_lv = (const float*)d_in[13];
    const float* tok_lp = (const float*)d_in[14];
    float* outp = (float*)d_out;

    cudaFuncSetAttribute(gemm_tf32, cudaFuncAttributeMaxDynamicSharedMemorySize, GNST * GSTAGE);
    cudaFuncSetAttribute(attn_tf32, cudaFuncAttributeMaxDynamicSharedMemorySize, 3 * ASTG);

    cudaStream_t sB;
    cudaStreamCreateWithFlags(&sB, cudaStreamNonBlocking);
    cudaEvent_t evFork, evProbs, evStats;
    cudaEventCreateWithFlags(&evFork, cudaEventDisableTiming);
    cudaEventCreateWithFlags(&evProbs, cudaEventDisableTiming);
    cudaEventCreateWithFlags(&evStats, cudaEventDisableTiming);

    cudaEventRecord(evFork, 0);
    cudaStreamWaitEvent(sB, evFork, 0);

    // branch B: zero -> clustering -> pack_pk -> (evProbs) -> stats -> (evStats)
    zero_kernel<<<1, 256, 0, sB>>>();
    clustering_kernel<<<dim3(2 * BB * HH, 4), 256, 0, sB>>>(query, key, tok_mu, tok_lv, tok_lp);
    pack_pk<<<512, 256, 0, sB>>>();
    cudaEventRecord(evProbs, sB);
    stats_kernel<<<256, 256, 0, sB>>>();
    cudaEventRecord(evStats, sB);

    // branch A: pack_w -> QKV gemm
    PArgs pw;
    pw.W[0] = Wq; pw.W[1] = Wk; pw.W[2] = Wv; pw.W[3] = Wo;
    pack_w<<<256, 256>>>(pw);

    GArgs qkv;
    qkv.A[0] = query; qkv.A[1] = key; qkv.A[2] = value;
    qkv.Bi[0] = bq;   qkv.Bi[1] = bk; qkv.Bi[2] = bv;
    qkv.sc[0] = 0.125f; qkv.sc[1] = 1.f; qkv.sc[2] = 1.f;
    qkv.md[0] = 0; qkv.md[1] = 1; qkv.md[2] = 2;
    qkv.ws[0] = 0; qkv.ws[1] = 1; qkv.ws[2] = 2;
    qkv.outp = nullptr;
    gemm_tf32<<<dim3(4, 32, 3), 256, GNST * GSTAGE>>>(qkv);

    cudaStreamWaitEvent(0, evProbs, 0);
    attn_tf32<<<dim3(BB * HH, LL / 128), 256, 3 * ASTG>>>(pmask);

    GArgs og;
    og.A[0] = nullptr; og.A[1] = nullptr; og.A[2] = nullptr;
    og.Bi[0] = bo; og.Bi[1] = bo; og.Bi[2] = bo;
    og.sc[0] = 1.f; og.sc[1] = 1.f; og.sc[2] = 1.f;
    og.md[0] = 3; og.md[1] = 3; og.md[2] = 3;
    og.ws[0] = 3; og.ws[1] = 3; og.ws[2] = 3;
    og.outp = outp;
    gemm_tf32<<<dim3(4, 32, 1), 256, GNST * GSTAGE>>>(og);

    cudaStreamWaitEvent(0, evStats, 0);
    finalize_kernel<<<1, 32>>>(outp, out_size);
}